// round 1
// baseline (speedup 1.0000x reference)
#include <cuda_runtime.h>
#include <cuda_bf16.h>
#include <math.h>

#define SS 1024
#define DD 128
#define NBH 24
#define NH 12

// scratch planes: scores (causal-masked QK^T) and logits (conv*scale)
__device__ float g_scores[(size_t)NBH * SS * SS];
__device__ float g_logits[(size_t)NBH * SS * SS];

// ---------------------------------------------------------------------------
// Kernel 1: scores = Q @ K^T with causal zero-fill (zeros above diagonal,
// matching the reference which zeroes scores BEFORE the conv).
// 64x64 tiles, K-dim chunked by 64, transposed smem, 4x4 micro-tiles.
// ---------------------------------------------------------------------------
__global__ __launch_bounds__(256) void qk_gemm_kernel(
    const float* __restrict__ Q, const float* __restrict__ K)
{
    const int kt = blockIdx.x;
    const int qt = blockIdx.y;
    const int bh = blockIdx.z;
    float* out = g_scores + (size_t)bh * SS * SS;
    const int tid = threadIdx.x;

    if (kt > qt) {
        // strictly-upper tile: fill zeros (conv reads these as 0)
        float4 z = make_float4(0.f, 0.f, 0.f, 0.f);
        for (int i = tid; i < 64 * 16; i += 256) {
            int r = i / 16, c4 = i % 16;
            *(float4*)&out[(size_t)(qt * 64 + r) * SS + kt * 64 + c4 * 4] = z;
        }
        return;
    }

    __shared__ float QsT[64][68];  // [d][row], padded
    __shared__ float KsT[64][68];

    float acc[4][4] = {};
    const int ty = tid / 16, tx = tid % 16;
    const int r0 = ty * 4, c0 = tx * 4;

    const float* Qb = Q + ((size_t)bh * SS + (size_t)qt * 64) * DD;
    const float* Kb = K + ((size_t)bh * SS + (size_t)kt * 64) * DD;

    for (int ch = 0; ch < 2; ch++) {
        // load 64 rows x 64 d (transposed into smem)
        for (int i = tid; i < 64 * 16; i += 256) {
            int row = i / 16, d4 = i % 16;
            float4 v = *(const float4*)&Qb[row * DD + ch * 64 + d4 * 4];
            QsT[d4 * 4 + 0][row] = v.x;
            QsT[d4 * 4 + 1][row] = v.y;
            QsT[d4 * 4 + 2][row] = v.z;
            QsT[d4 * 4 + 3][row] = v.w;
            float4 u = *(const float4*)&Kb[row * DD + ch * 64 + d4 * 4];
            KsT[d4 * 4 + 0][row] = u.x;
            KsT[d4 * 4 + 1][row] = u.y;
            KsT[d4 * 4 + 2][row] = u.z;
            KsT[d4 * 4 + 3][row] = u.w;
        }
        __syncthreads();

        #pragma unroll 8
        for (int dd = 0; dd < 64; dd++) {
            float4 qv = *(float4*)&QsT[dd][r0];
            float4 kv = *(float4*)&KsT[dd][c0];
            acc[0][0] += qv.x * kv.x; acc[0][1] += qv.x * kv.y;
            acc[0][2] += qv.x * kv.z; acc[0][3] += qv.x * kv.w;
            acc[1][0] += qv.y * kv.x; acc[1][1] += qv.y * kv.y;
            acc[1][2] += qv.y * kv.z; acc[1][3] += qv.y * kv.w;
            acc[2][0] += qv.z * kv.x; acc[2][1] += qv.z * kv.y;
            acc[2][2] += qv.z * kv.z; acc[2][3] += qv.z * kv.w;
            acc[3][0] += qv.w * kv.x; acc[3][1] += qv.w * kv.y;
            acc[3][2] += qv.w * kv.z; acc[3][3] += qv.w * kv.w;
        }
        __syncthreads();
    }

    // write (mask above-diagonal on diagonal tiles)
    #pragma unroll
    for (int i = 0; i < 4; i++) {
        int q = qt * 64 + r0 + i;
        float4 o;
        float* po = &o.x;
        #pragma unroll
        for (int j = 0; j < 4; j++) {
            int k = kt * 64 + c0 + j;
            float v = acc[i][j];
            if (kt == qt && k > q) v = 0.f;
            po[j] = v;
        }
        *(float4*)&out[(size_t)q * SS + kt * 64 + c0] = o;
    }
}

// ---------------------------------------------------------------------------
// Kernel 2: logits = conv2d(scores, W[h]) * scale
// conv[q,k] = sum_{dq=0..5,dk=0..10} W[h,dq,dk] * S[q-5+dq, k-5+dk]
// tile: 32 q-rows x 128 k-cols, halo (5 up, 5/5 sideways) in smem.
// Skips tiles strictly above the diagonal (kernel 3 never reads them).
// ---------------------------------------------------------------------------
__global__ __launch_bounds__(256) void conv_kernel(const float* __restrict__ W)
{
    const int kt = blockIdx.x;   // 0..7   (128 cols)
    const int qt = blockIdx.y;   // 0..31  (32 rows)
    const int bh = blockIdx.z;
    const int k0 = kt * 128, q0 = qt * 32;
    if (k0 > q0 + 31) return;

    const float* Sb = g_scores + (size_t)bh * SS * SS;
    float* Lb = g_logits + (size_t)bh * SS * SS;

    __shared__ float sh[37][140];   // rows q0-5..q0+31, cols k0-5..k0+132
    __shared__ float ws[66];

    const int tid = threadIdx.x;
    const int h = bh % NH;
    if (tid < 66) ws[tid] = W[h * 66 + tid];

    for (int i = tid; i < 37 * 138; i += 256) {
        int rr = i / 138, cc = i % 138;
        int q = q0 - 5 + rr;
        int k = k0 - 5 + cc;
        float v = 0.f;
        if (q >= 0 && k >= 0 && k < SS) v = Sb[(size_t)q * SS + k];
        sh[rr][cc] = v;
    }
    __syncthreads();

    const int r = tid / 8;          // 0..31
    const int c0 = (tid % 8) * 16;  // 0..112
    float out[16] = {};

    for (int dq = 0; dq < 6; dq++) {
        float win[26];
        #pragma unroll
        for (int t = 0; t < 26; t++) win[t] = sh[r + dq][c0 + t];
        #pragma unroll
        for (int dk = 0; dk < 11; dk++) {
            float w = ws[dq * 11 + dk];
            #pragma unroll
            for (int j = 0; j < 16; j++) out[j] += w * win[j + dk];
        }
    }

    const float scale = 0.088388347648318447f;  // 1/sqrt(128)
    const int q = q0 + r;
    #pragma unroll
    for (int j4 = 0; j4 < 4; j4++) {
        float4 o = make_float4(out[j4*4+0]*scale, out[j4*4+1]*scale,
                               out[j4*4+2]*scale, out[j4*4+3]*scale);
        *(float4*)&Lb[(size_t)q * SS + k0 + c0 + j4 * 4] = o;
    }
}

// ---------------------------------------------------------------------------
// Kernel 3: softmax(logits, causal) @ V
// Block: 32 q-rows, 256 threads. Two-pass max/sum (8 lanes per row),
// then PV over 64-key chunks with V and P staged in smem.
// Masks k>q at read (above-diagonal logits were never written).
// ---------------------------------------------------------------------------
__global__ __launch_bounds__(256) void softmax_pv_kernel(
    const float* __restrict__ V, float* __restrict__ O)
{
    const int qt = blockIdx.x;    // 0..31
    const int bh = blockIdx.y;
    const int q0 = qt * 32;

    const float* Lb = g_logits + (size_t)bh * SS * SS;
    const float* Vb = V + (size_t)bh * SS * DD;
    float* Ob = O + (size_t)bh * SS * DD;

    const int tid = threadIdx.x;
    const int r = tid / 8, l8 = tid % 8;
    const int q = q0 + r;

    __shared__ float Vs[64][128];
    __shared__ float Ps[32][64];
    __shared__ float rowM[32], rowInv[32];

    // pass 1: row max
    float m = -1e30f;
    for (int k = l8; k <= q; k += 8) m = fmaxf(m, Lb[(size_t)q * SS + k]);
    #pragma unroll
    for (int o = 4; o; o >>= 1) m = fmaxf(m, __shfl_xor_sync(0xffffffffu, m, o));

    // pass 2: sum of exp
    float ssum = 0.f;
    for (int k = l8; k <= q; k += 8) ssum += __expf(Lb[(size_t)q * SS + k] - m);
    #pragma unroll
    for (int o = 4; o; o >>= 1) ssum += __shfl_xor_sync(0xffffffffu, ssum, o);

    if (l8 == 0) { rowM[r] = m; rowInv[r] = 1.f / ssum; }
    __syncthreads();

    // PV over 64-key chunks
    float acc[16] = {};
    const int d0 = l8 * 16;
    const int nk = q0 + 32;  // max key index + 1 used by this block (<= SS)

    for (int kc = 0; kc < nk; kc += 64) {
        // stage V chunk
        for (int i = tid; i < 64 * 32; i += 256) {
            int kr = i / 32, c4 = i % 32;
            *(float4*)&Vs[kr][c4 * 4] =
                *(const float4*)&Vb[(size_t)(kc + kr) * DD + c4 * 4];
        }
        // stage P chunk
        for (int i = tid; i < 32 * 64; i += 256) {
            int r2 = i / 64, k2 = i % 64;
            int qq = q0 + r2, kk2 = kc + k2;
            float p = 0.f;
            if (kk2 <= qq)
                p = __expf(Lb[(size_t)qq * SS + kk2] - rowM[r2]) * rowInv[r2];
            Ps[r2][k2] = p;
        }
        __syncthreads();

        #pragma unroll 4
        for (int k2 = 0; k2 < 64; k2++) {
            float p = Ps[r][k2];
            #pragma unroll
            for (int j4 = 0; j4 < 4; j4++) {
                float4 v = *(float4*)&Vs[k2][d0 + j4 * 4];
                acc[j4 * 4 + 0] += p * v.x;
                acc[j4 * 4 + 1] += p * v.y;
                acc[j4 * 4 + 2] += p * v.z;
                acc[j4 * 4 + 3] += p * v.w;
            }
        }
        __syncthreads();
    }

    #pragma unroll
    for (int j4 = 0; j4 < 4; j4++) {
        float4 o = make_float4(acc[j4*4+0], acc[j4*4+1], acc[j4*4+2], acc[j4*4+3]);
        *(float4*)&Ob[(size_t)q * DD + d0 + j4 * 4] = o;
    }
}

// ---------------------------------------------------------------------------
extern "C" void kernel_launch(void* const* d_in, const int* in_sizes, int n_in,
                              void* d_out, int out_size)
{
    const float* Q = (const float*)d_in[0];
    const float* K = (const float*)d_in[1];
    const float* V = (const float*)d_in[2];
    const float* W = (const float*)d_in[3];
    float* O = (float*)d_out;

    dim3 g1(16, 16, NBH);
    qk_gemm_kernel<<<g1, 256>>>(Q, K);

    dim3 g2(8, 32, NBH);
    conv_kernel<<<g2, 256>>>(W);

    dim3 g3(32, NBH);
    softmax_pv_kernel<<<g3, 256>>>(V, O);
}

// round 2
// speedup vs baseline: 2.8960x; 2.8960x over previous
#include <cuda_runtime.h>
#include <cuda_bf16.h>
#include <math.h>

#define SS 1024
#define DD 128
#define NBH 24
#define NH 12

// scratch planes: scores (raw QK^T, lower triangle only) and logits (conv*scale)
__device__ float g_scores[(size_t)NBH * SS * SS];
__device__ float g_logits[(size_t)NBH * SS * SS];

// ---------------------------------------------------------------------------
// Kernel 1: scores = Q @ K^T, lower-triangle tiles only (conv masks k>q at
// load, so upper triangle is never written or read).
// 128x128 tiles, BK=16, 8x8 register micro-tiles, 256 threads.
// ---------------------------------------------------------------------------
__global__ __launch_bounds__(256) void qk_gemm_kernel(
    const float* __restrict__ Q, const float* __restrict__ K)
{
    const int kt = blockIdx.x;   // 0..7
    const int qt = blockIdx.y;   // 0..7
    if (kt > qt) return;         // strictly-upper tile: skip entirely
    const int bh = blockIdx.z;

    float* out = g_scores + (size_t)bh * SS * SS;
    const int tid = threadIdx.x;

    __shared__ float QsT[16][132];  // [k][row]
    __shared__ float KsT[16][132];  // [k][col]

    float acc[8][8] = {};

    const int ty = tid / 16, tx = tid % 16;
    const int r0 = ty * 8, c0 = tx * 8;

    const float* Qb = Q + ((size_t)bh * SS + (size_t)qt * 128) * DD;
    const float* Kb = K + ((size_t)bh * SS + (size_t)kt * 128) * DD;

    const int lr = tid / 4;        // 0..63
    const int lc4 = tid % 4;       // 0..3 (float4 within 16-wide chunk)

    for (int ch = 0; ch < 8; ch++) {
        // load 128 rows x 16 d chunk of Q and K, transposed into smem
        #pragma unroll
        for (int rep = 0; rep < 2; rep++) {
            int rr = lr + rep * 64;
            float4 v = *(const float4*)&Qb[(size_t)rr * DD + ch * 16 + lc4 * 4];
            QsT[lc4 * 4 + 0][rr] = v.x;
            QsT[lc4 * 4 + 1][rr] = v.y;
            QsT[lc4 * 4 + 2][rr] = v.z;
            QsT[lc4 * 4 + 3][rr] = v.w;
            float4 u = *(const float4*)&Kb[(size_t)rr * DD + ch * 16 + lc4 * 4];
            KsT[lc4 * 4 + 0][rr] = u.x;
            KsT[lc4 * 4 + 1][rr] = u.y;
            KsT[lc4 * 4 + 2][rr] = u.z;
            KsT[lc4 * 4 + 3][rr] = u.w;
        }
        __syncthreads();

        #pragma unroll
        for (int k = 0; k < 16; k++) {
            float4 a0 = *(float4*)&QsT[k][r0];
            float4 a1 = *(float4*)&QsT[k][r0 + 4];
            float4 b0 = *(float4*)&KsT[k][c0];
            float4 b1 = *(float4*)&KsT[k][c0 + 4];
            float av[8] = {a0.x, a0.y, a0.z, a0.w, a1.x, a1.y, a1.z, a1.w};
            float bv[8] = {b0.x, b0.y, b0.z, b0.w, b1.x, b1.y, b1.z, b1.w};
            #pragma unroll
            for (int i = 0; i < 8; i++)
                #pragma unroll
                for (int j = 0; j < 8; j++)
                    acc[i][j] += av[i] * bv[j];
        }
        __syncthreads();
    }

    // write 8x8 block (no masking needed; conv masks at read)
    #pragma unroll
    for (int i = 0; i < 8; i++) {
        int q = qt * 128 + r0 + i;
        float* po = &out[(size_t)q * SS + kt * 128 + c0];
        *(float4*)&po[0] = make_float4(acc[i][0], acc[i][1], acc[i][2], acc[i][3]);
        *(float4*)&po[4] = make_float4(acc[i][4], acc[i][5], acc[i][6], acc[i][7]);
    }
}

// ---------------------------------------------------------------------------
// Kernel 2: logits = conv2d(causal_mask(scores), W[h]) * scale
// Mask applied at load: score(q,k) valid only for 0<=k<=q.
// tile: 32 q-rows x 128 k-cols, halo (5 up, 5 sideways) in smem.
// ---------------------------------------------------------------------------
__global__ __launch_bounds__(256) void conv_kernel(const float* __restrict__ W)
{
    const int kt = blockIdx.x;   // 0..7   (128 cols)
    const int qt = blockIdx.y;   // 0..31  (32 rows)
    const int bh = blockIdx.z;
    const int k0 = kt * 128, q0 = qt * 32;
    if (k0 > q0 + 31) return;

    const float* Sb = g_scores + (size_t)bh * SS * SS;
    float* Lb = g_logits + (size_t)bh * SS * SS;

    __shared__ float sh[37][140];   // rows q0-5..q0+31, cols k0-5..k0+132
    __shared__ float ws[66];

    const int tid = threadIdx.x;
    const int h = bh % NH;
    if (tid < 66) ws[tid] = W[h * 66 + tid];

    for (int i = tid; i < 37 * 138; i += 256) {
        int rr = i / 138, cc = i % 138;
        int q = q0 - 5 + rr;
        int k = k0 - 5 + cc;
        float v = 0.f;
        if (q >= 0 && k >= 0 && k <= q) v = Sb[(size_t)q * SS + k];
        sh[rr][cc] = v;
    }
    __syncthreads();

    const int r = tid / 8;          // 0..31
    const int c0 = (tid % 8) * 16;  // 0..112
    float out[16] = {};

    for (int dq = 0; dq < 6; dq++) {
        float win[26];
        #pragma unroll
        for (int t = 0; t < 26; t++) win[t] = sh[r + dq][c0 + t];
        #pragma unroll
        for (int dk = 0; dk < 11; dk++) {
            float w = ws[dq * 11 + dk];
            #pragma unroll
            for (int j = 0; j < 16; j++) out[j] += w * win[j + dk];
        }
    }

    const float scale = 0.088388347648318447f;  // 1/sqrt(128)
    const int q = q0 + r;
    #pragma unroll
    for (int j4 = 0; j4 < 4; j4++) {
        float4 o = make_float4(out[j4*4+0]*scale, out[j4*4+1]*scale,
                               out[j4*4+2]*scale, out[j4*4+3]*scale);
        *(float4*)&Lb[(size_t)q * SS + k0 + c0 + j4 * 4] = o;
    }
}

// ---------------------------------------------------------------------------
// Kernel 3: softmax(logits, causal) @ V
// Block: 64 q-rows x 128 d, 256 threads, each thread owns a 4x8 (q x d)
// micro-tile. Two-pass max/sum (1 warp scans 8 rows), then PV over 32-key
// chunks: P transposed [k][q] in smem (broadcast loads), V [k][d].
// ---------------------------------------------------------------------------
__global__ __launch_bounds__(256) void softmax_pv_kernel(
    const float* __restrict__ V, float* __restrict__ O)
{
    const int qt = blockIdx.x;    // 0..15
    const int bh = blockIdx.y;
    const int q0 = qt * 64;

    const float* Lb = g_logits + (size_t)bh * SS * SS;
    const float* Vb = V + (size_t)bh * SS * DD;
    float* Ob = O + (size_t)bh * SS * DD;

    const int tid = threadIdx.x;
    const int warp = tid >> 5, lane = tid & 31;

    __shared__ float rowM[64], rowInv[64];
    __shared__ float Ps[32][68];    // [k][q], padded
    __shared__ float Vs[32][132];   // [k][d], padded

    // ---- phase A: row max & sum (each warp scans 8 rows) ----
    #pragma unroll 1
    for (int i = 0; i < 8; i++) {
        const int r = warp * 8 + i;
        const int q = q0 + r;
        const float* Lrow = &Lb[(size_t)q * SS];

        float m = -1e30f;
        for (int k = lane; k <= q; k += 32) m = fmaxf(m, Lrow[k]);
        #pragma unroll
        for (int o = 16; o; o >>= 1) m = fmaxf(m, __shfl_xor_sync(0xffffffffu, m, o));

        float ssum = 0.f;
        for (int k = lane; k <= q; k += 32) ssum += __expf(Lrow[k] - m);
        #pragma unroll
        for (int o = 16; o; o >>= 1) ssum += __shfl_xor_sync(0xffffffffu, ssum, o);

        if (lane == 0) { rowM[r] = m; rowInv[r] = 1.f / ssum; }
    }
    __syncthreads();

    // ---- phase B: PV ----
    const int r0 = (tid >> 4) * 4;   // 0..60
    const int d0 = (tid & 15) * 8;   // 0..120
    float acc[4][8] = {};

    const int nk = q0 + 64;

    for (int kc = 0; kc < nk; kc += 32) {
        // stage V chunk: 32 keys x 128 d
        for (int i = tid; i < 32 * 32; i += 256) {
            int kr = i >> 5, c4 = i & 31;
            *(float4*)&Vs[kr][c4 * 4] =
                *(const float4*)&Vb[(size_t)(kc + kr) * DD + c4 * 4];
        }
        // stage P chunk transposed: Ps[k][q]; coalesced logit reads
        for (int i = tid; i < 32 * 64; i += 256) {
            int k2 = i & 31, r = i >> 5;
            int kk = kc + k2, qq = q0 + r;
            float p = 0.f;
            if (kk <= qq)
                p = __expf(Lb[(size_t)qq * SS + kk] - rowM[r]) * rowInv[r];
            Ps[k2][r] = p;
        }
        __syncthreads();

        #pragma unroll
        for (int k2 = 0; k2 < 32; k2++) {
            float4 p = *(float4*)&Ps[k2][r0];
            float4 va = *(float4*)&Vs[k2][d0];
            float4 vb = *(float4*)&Vs[k2][d0 + 4];
            float pv[4] = {p.x, p.y, p.z, p.w};
            float vv[8] = {va.x, va.y, va.z, va.w, vb.x, vb.y, vb.z, vb.w};
            #pragma unroll
            for (int i = 0; i < 4; i++)
                #pragma unroll
                for (int j = 0; j < 8; j++)
                    acc[i][j] += pv[i] * vv[j];
        }
        __syncthreads();
    }

    #pragma unroll
    for (int i = 0; i < 4; i++) {
        int q = q0 + r0 + i;
        float* po = &Ob[(size_t)q * DD + d0];
        *(float4*)&po[0] = make_float4(acc[i][0], acc[i][1], acc[i][2], acc[i][3]);
        *(float4*)&po[4] = make_float4(acc[i][4], acc[i][5], acc[i][6], acc[i][7]);
    }
}

// ---------------------------------------------------------------------------
extern "C" void kernel_launch(void* const* d_in, const int* in_sizes, int n_in,
                              void* d_out, int out_size)
{
    const float* Q = (const float*)d_in[0];
    const float* K = (const float*)d_in[1];
    const float* V = (const float*)d_in[2];
    const float* W = (const float*)d_in[3];
    float* O = (float*)d_out;

    dim3 g1(8, 8, NBH);
    qk_gemm_kernel<<<g1, 256>>>(Q, K);

    dim3 g2(8, 32, NBH);
    conv_kernel<<<g2, 256>>>(W);

    dim3 g3(16, NBH);
    softmax_pv_kernel<<<g3, 256>>>(V, O);
}

// round 3
// speedup vs baseline: 3.2669x; 1.1281x over previous
#include <cuda_runtime.h>
#include <cuda_bf16.h>
#include <math.h>

#define SS 1024
#define DD 128
#define NBH 24
#define NH 12

// scratch planes: scores (raw QK^T, lower triangle only) and logits (conv*scale)
__device__ float g_scores[(size_t)NBH * SS * SS];
__device__ float g_logits[(size_t)NBH * SS * SS];

// fast exp on the FMA pipe: exp(x) = 2^(x*log2e), range-reduced, degree-6 poly
__device__ __forceinline__ float fexp(float x) {
    float y = x * 1.4426950408889634f;
    y = fminf(fmaxf(y, -120.f), 120.f);
    float fy = floorf(y);
    float f = y - fy;
    float p = 1.5403530e-4f;               // ln2^6/6!
    p = fmaf(p, f, 1.3333558e-3f);         // ln2^5/5!
    p = fmaf(p, f, 9.6181291e-3f);         // ln2^4/4!
    p = fmaf(p, f, 5.5504109e-2f);         // ln2^3/3!
    p = fmaf(p, f, 2.4022651e-1f);         // ln2^2/2!
    p = fmaf(p, f, 6.9314718e-1f);         // ln2
    p = fmaf(p, f, 1.0f);
    int e = (int)fy;
    return p * __int_as_float((e + 127) << 23);
}

// ---------------------------------------------------------------------------
// Kernel 1: scores = Q @ K^T, lower-triangle tiles only.
// 128x128 tiles, BK=16, 8x8 register micro-tiles, 256 threads.
// ---------------------------------------------------------------------------
__global__ __launch_bounds__(256) void qk_gemm_kernel(
    const float* __restrict__ Q, const float* __restrict__ K)
{
    const int kt = blockIdx.x;
    const int qt = blockIdx.y;
    if (kt > qt) return;
    const int bh = blockIdx.z;

    float* out = g_scores + (size_t)bh * SS * SS;
    const int tid = threadIdx.x;

    __shared__ float QsT[16][132];
    __shared__ float KsT[16][132];

    float acc[8][8] = {};

    const int ty = tid / 16, tx = tid % 16;
    const int r0 = ty * 8, c0 = tx * 8;

    const float* Qb = Q + ((size_t)bh * SS + (size_t)qt * 128) * DD;
    const float* Kb = K + ((size_t)bh * SS + (size_t)kt * 128) * DD;

    const int lr = tid / 4;
    const int lc4 = tid % 4;

    for (int ch = 0; ch < 8; ch++) {
        #pragma unroll
        for (int rep = 0; rep < 2; rep++) {
            int rr = lr + rep * 64;
            float4 v = *(const float4*)&Qb[(size_t)rr * DD + ch * 16 + lc4 * 4];
            QsT[lc4 * 4 + 0][rr] = v.x;
            QsT[lc4 * 4 + 1][rr] = v.y;
            QsT[lc4 * 4 + 2][rr] = v.z;
            QsT[lc4 * 4 + 3][rr] = v.w;
            float4 u = *(const float4*)&Kb[(size_t)rr * DD + ch * 16 + lc4 * 4];
            KsT[lc4 * 4 + 0][rr] = u.x;
            KsT[lc4 * 4 + 1][rr] = u.y;
            KsT[lc4 * 4 + 2][rr] = u.z;
            KsT[lc4 * 4 + 3][rr] = u.w;
        }
        __syncthreads();

        #pragma unroll
        for (int k = 0; k < 16; k++) {
            float4 a0 = *(float4*)&QsT[k][r0];
            float4 a1 = *(float4*)&QsT[k][r0 + 4];
            float4 b0 = *(float4*)&KsT[k][c0];
            float4 b1 = *(float4*)&KsT[k][c0 + 4];
            float av[8] = {a0.x, a0.y, a0.z, a0.w, a1.x, a1.y, a1.z, a1.w};
            float bv[8] = {b0.x, b0.y, b0.z, b0.w, b1.x, b1.y, b1.z, b1.w};
            #pragma unroll
            for (int i = 0; i < 8; i++)
                #pragma unroll
                for (int j = 0; j < 8; j++)
                    acc[i][j] += av[i] * bv[j];
        }
        __syncthreads();
    }

    #pragma unroll
    for (int i = 0; i < 8; i++) {
        int q = qt * 128 + r0 + i;
        float* po = &out[(size_t)q * SS + kt * 128 + c0];
        *(float4*)&po[0] = make_float4(acc[i][0], acc[i][1], acc[i][2], acc[i][3]);
        *(float4*)&po[4] = make_float4(acc[i][4], acc[i][5], acc[i][6], acc[i][7]);
    }
}

// ---------------------------------------------------------------------------
// Kernel 2: logits = conv2d(causal_mask(scores), W[h]) * scale
// ---------------------------------------------------------------------------
__global__ __launch_bounds__(256) void conv_kernel(const float* __restrict__ W)
{
    const int kt = blockIdx.x;
    const int qt = blockIdx.y;
    const int bh = blockIdx.z;
    const int k0 = kt * 128, q0 = qt * 32;
    if (k0 > q0 + 31) return;

    const float* Sb = g_scores + (size_t)bh * SS * SS;
    float* Lb = g_logits + (size_t)bh * SS * SS;

    __shared__ float sh[37][140];
    __shared__ float ws[66];

    const int tid = threadIdx.x;
    const int h = bh % NH;
    if (tid < 66) ws[tid] = W[h * 66 + tid];

    for (int i = tid; i < 37 * 138; i += 256) {
        int rr = i / 138, cc = i % 138;
        int q = q0 - 5 + rr;
        int k = k0 - 5 + cc;
        float v = 0.f;
        if (q >= 0 && k >= 0 && k <= q) v = Sb[(size_t)q * SS + k];
        sh[rr][cc] = v;
    }
    __syncthreads();

    const int r = tid / 8;
    const int c0 = (tid % 8) * 16;
    float out[16] = {};

    for (int dq = 0; dq < 6; dq++) {
        float win[26];
        #pragma unroll
        for (int t = 0; t < 26; t++) win[t] = sh[r + dq][c0 + t];
        #pragma unroll
        for (int dk = 0; dk < 11; dk++) {
            float w = ws[dq * 11 + dk];
            #pragma unroll
            for (int j = 0; j < 16; j++) out[j] += w * win[j + dk];
        }
    }

    const float scale = 0.088388347648318447f;
    const int q = q0 + r;
    #pragma unroll
    for (int j4 = 0; j4 < 4; j4++) {
        float4 o = make_float4(out[j4*4+0]*scale, out[j4*4+1]*scale,
                               out[j4*4+2]*scale, out[j4*4+3]*scale);
        *(float4*)&Lb[(size_t)q * SS + k0 + c0 + j4 * 4] = o;
    }
}

// ---------------------------------------------------------------------------
// Kernel 3: single-pass no-max softmax @ V.
// O_row = (sum_k e^l V_k) / (sum_k e^l); logits bounded (~|l|<6) so no
// running max needed. One exp per element, on the FMA pipe.
// Block: 64 q-rows x 128 d, 256 threads, 4x8 (q x d) micro-tiles.
// ---------------------------------------------------------------------------
__global__ __launch_bounds__(256) void softmax_pv_kernel(
    const float* __restrict__ V, float* __restrict__ O)
{
    const int qt = blockIdx.x;    // 0..15
    const int bh = blockIdx.y;
    const int q0 = qt * 64;

    const float* Lb = g_logits + (size_t)bh * SS * SS;
    const float* Vb = V + (size_t)bh * SS * DD;
    float* Ob = O + (size_t)bh * SS * DD;

    const int tid = threadIdx.x;
    const int warp = tid >> 5, lane = tid & 31;

    __shared__ float Ps[64][33];    // [row][key], pad 33 -> conflict-free stores
    __shared__ float Vs[32][132];   // [key][d]
    __shared__ float rowSum[64];

    float psum[8] = {};
    const int r0 = (tid >> 4) * 4;   // 0..60
    const int d0 = (tid & 15) * 8;   // 0..120
    float acc[4][8] = {};

    const int nk = q0 + 64;

    for (int kc = 0; kc < nk; kc += 32) {
        // stage V chunk: 32 keys x 128 d
        for (int i = tid; i < 32 * 32; i += 256) {
            int kr = i >> 5, c4 = i & 31;
            *(float4*)&Vs[kr][c4 * 4] =
                *(const float4*)&Vb[(size_t)(kc + kr) * DD + c4 * 4];
        }
        // stage unnormalized P = exp(l); thread (warp,lane) owns rows warp+8j,
        // key kc+lane. Coalesced logit reads; per-thread row partial sums.
        const int kk = kc + lane;
        #pragma unroll
        for (int j = 0; j < 8; j++) {
            int r = warp + 8 * j;
            int qq = q0 + r;
            float e = 0.f;
            if (kk <= qq) e = fexp(Lb[(size_t)qq * SS + kk]);
            psum[j] += e;
            Ps[r][lane] = e;
        }
        __syncthreads();

        #pragma unroll
        for (int k2 = 0; k2 < 32; k2++) {
            float pv[4];
            #pragma unroll
            for (int i = 0; i < 4; i++) pv[i] = Ps[r0 + i][k2];
            float4 va = *(float4*)&Vs[k2][d0];
            float4 vb = *(float4*)&Vs[k2][d0 + 4];
            float vv[8] = {va.x, va.y, va.z, va.w, vb.x, vb.y, vb.z, vb.w};
            #pragma unroll
            for (int i = 0; i < 4; i++)
                #pragma unroll
                for (int j = 0; j < 8; j++)
                    acc[i][j] += pv[i] * vv[j];
        }
        __syncthreads();
    }

    // reduce per-row sums across lanes
    #pragma unroll
    for (int j = 0; j < 8; j++) {
        float s = psum[j];
        #pragma unroll
        for (int o = 16; o; o >>= 1) s += __shfl_xor_sync(0xffffffffu, s, o);
        if (lane == 0) rowSum[warp + 8 * j] = s;
    }
    __syncthreads();

    #pragma unroll
    for (int i = 0; i < 4; i++) {
        int q = q0 + r0 + i;
        float inv = 1.f / rowSum[r0 + i];
        float* po = &Ob[(size_t)q * DD + d0];
        *(float4*)&po[0] = make_float4(acc[i][0]*inv, acc[i][1]*inv,
                                       acc[i][2]*inv, acc[i][3]*inv);
        *(float4*)&po[4] = make_float4(acc[i][4]*inv, acc[i][5]*inv,
                                       acc[i][6]*inv, acc[i][7]*inv);
    }
}

// ---------------------------------------------------------------------------
extern "C" void kernel_launch(void* const* d_in, const int* in_sizes, int n_in,
                              void* d_out, int out_size)
{
    const float* Q = (const float*)d_in[0];
    const float* K = (const float*)d_in[1];
    const float* V = (const float*)d_in[2];
    const float* W = (const float*)d_in[3];
    float* O = (float*)d_out;

    dim3 g1(8, 8, NBH);
    qk_gemm_kernel<<<g1, 256>>>(Q, K);

    dim3 g2(8, 32, NBH);
    conv_kernel<<<g2, 256>>>(W);

    dim3 g3(16, NBH);
    softmax_pv_kernel<<<g3, 256>>>(V, O);
}

// round 5
// speedup vs baseline: 3.3217x; 1.0167x over previous
#include <cuda_runtime.h>
#include <cuda_bf16.h>
#include <math.h>
#include <stdint.h>

#define SS 1024
#define DD 128
#define NBH 24
#define NH 12

// scratch planes: scores (raw QK^T, lower triangle only) and logits (conv*scale)
__device__ float g_scores[(size_t)NBH * SS * SS];
__device__ float g_logits[(size_t)NBH * SS * SS];

__device__ __forceinline__ uint32_t smem_u32(const void* p) {
    uint32_t a;
    asm("{ .reg .u64 t; cvta.to.shared.u64 t, %1; cvt.u32.u64 %0, t; }"
        : "=r"(a) : "l"(p));
    return a;
}

#define LDMATRIX_X4(r0, r1, r2, r3, addr) \
    asm volatile("ldmatrix.sync.aligned.m8n8.x4.shared.b16 {%0,%1,%2,%3}, [%4];" \
                 : "=r"(r0), "=r"(r1), "=r"(r2), "=r"(r3) : "r"(addr))

#define MMA_BF16(d, a, b) \
    asm volatile("mma.sync.aligned.m16n8k16.row.col.f32.bf16.bf16.f32 " \
                 "{%0,%1,%2,%3}, {%4,%5,%6,%7}, {%8,%9}, {%0,%1,%2,%3};" \
                 : "+f"((d)[0]), "+f"((d)[1]), "+f"((d)[2]), "+f"((d)[3]) \
                 : "r"((a)[0]), "r"((a)[1]), "r"((a)[2]), "r"((a)[3]), \
                   "r"((b)[0]), "r"((b)[1]))

// fast exp on the FMA pipe
__device__ __forceinline__ float fexp(float x) {
    float y = x * 1.4426950408889634f;
    y = fminf(fmaxf(y, -120.f), 120.f);
    float fy = floorf(y);
    float f = y - fy;
    float p = 1.5403530e-4f;
    p = fmaf(p, f, 1.3333558e-3f);
    p = fmaf(p, f, 9.6181291e-3f);
    p = fmaf(p, f, 5.5504109e-2f);
    p = fmaf(p, f, 2.4022651e-1f);
    p = fmaf(p, f, 6.9314718e-1f);
    p = fmaf(p, f, 1.0f);
    int e = (int)fy;
    return p * __int_as_float((e + 127) << 23);
}

// ---------------------------------------------------------------------------
// Kernel 1: scores = Q @ K^T via mma.sync bf16, split-bf16 3-term fp32 emu.
// 128x128 tile/block, 8 warps (4x2 grid), each warp 32x64.
// smem planes Qhi/Qlo/Khi/Klo: 128 rows x 136 bf16 (272B stride, conflict-free
// for ldmatrix).  S ~= Qhi*Khi + Qhi*Klo + Qlo*Khi  (fp32 accum).
// ---------------------------------------------------------------------------
#define LDE 136          // bf16 elements per smem row
#define PLANE (128 * LDE)  // elements per plane

__global__ __launch_bounds__(256) void qk_gemm_mma(
    const float* __restrict__ Q, const float* __restrict__ K)
{
    const int kt = blockIdx.x;
    const int qt = blockIdx.y;
    if (kt > qt) return;
    const int bh = blockIdx.z;

    extern __shared__ __align__(16) __nv_bfloat16 smem[];
    __nv_bfloat16* QH = smem;
    __nv_bfloat16* QL = smem + PLANE;
    __nv_bfloat16* KH = smem + 2 * PLANE;
    __nv_bfloat16* KL = smem + 3 * PLANE;

    const int tid = threadIdx.x;
    const float* Qb = Q + ((size_t)bh * SS + (size_t)qt * 128) * DD;
    const float* Kb = K + ((size_t)bh * SS + (size_t)kt * 128) * DD;

    // stage: load fp32, split into bf16 hi/lo
    for (int i = tid; i < 128 * 32; i += 256) {
        const int row = i >> 5, k = (i & 31) * 4;
        float4 v = *(const float4*)&Qb[(size_t)row * DD + k];
        __nv_bfloat16 h0 = __float2bfloat16(v.x), h1 = __float2bfloat16(v.y);
        __nv_bfloat16 h2 = __float2bfloat16(v.z), h3 = __float2bfloat16(v.w);
        __nv_bfloat162 hp0(h0, h1), hp1(h2, h3);
        __nv_bfloat162 lp0 = __floats2bfloat162_rn(v.x - __bfloat162float(h0),
                                                   v.y - __bfloat162float(h1));
        __nv_bfloat162 lp1 = __floats2bfloat162_rn(v.z - __bfloat162float(h2),
                                                   v.w - __bfloat162float(h3));
        *(uint2*)&QH[row * LDE + k] = make_uint2(*(uint32_t*)&hp0, *(uint32_t*)&hp1);
        *(uint2*)&QL[row * LDE + k] = make_uint2(*(uint32_t*)&lp0, *(uint32_t*)&lp1);

        float4 u = *(const float4*)&Kb[(size_t)row * DD + k];
        __nv_bfloat16 g0 = __float2bfloat16(u.x), g1 = __float2bfloat16(u.y);
        __nv_bfloat16 g2 = __float2bfloat16(u.z), g3 = __float2bfloat16(u.w);
        __nv_bfloat162 gp0(g0, g1), gp1(g2, g3);
        __nv_bfloat162 mp0 = __floats2bfloat162_rn(u.x - __bfloat162float(g0),
                                                   u.y - __bfloat162float(g1));
        __nv_bfloat162 mp1 = __floats2bfloat162_rn(u.z - __bfloat162float(g2),
                                                   u.w - __bfloat162float(g3));
        *(uint2*)&KH[row * LDE + k] = make_uint2(*(uint32_t*)&gp0, *(uint32_t*)&gp1);
        *(uint2*)&KL[row * LDE + k] = make_uint2(*(uint32_t*)&mp0, *(uint32_t*)&mp1);
    }
    __syncthreads();

    const int warp = tid >> 5, lane = tid & 31;
    const int m0 = (warp & 3) * 32;      // 4 m-tiles of 32
    const int n0 = (warp >> 2) * 64;     // 2 n-tiles of 64

    float acc[2][8][4] = {};

    // ldmatrix lane addressing offsets (element units)
    const int lrow = lane & 15;
    const int lgrp = lane >> 4;          // 0/1 -> +8 elements (16B)

    #pragma unroll
    for (int ks = 0; ks < 8; ks++) {
        const int kb = ks * 16;

        uint32_t ah[2][4], al[2][4];
        #pragma unroll
        for (int mi = 0; mi < 2; mi++) {
            uint32_t aH = smem_u32(&QH[(m0 + mi * 16 + lrow) * LDE + kb + lgrp * 8]);
            LDMATRIX_X4(ah[mi][0], ah[mi][1], ah[mi][2], ah[mi][3], aH);
            uint32_t aL = smem_u32(&QL[(m0 + mi * 16 + lrow) * LDE + kb + lgrp * 8]);
            LDMATRIX_X4(al[mi][0], al[mi][1], al[mi][2], al[mi][3], aL);
        }

        #pragma unroll
        for (int nfi = 0; nfi < 4; nfi++) {
            uint32_t bh4[4], bl4[4];
            uint32_t bHaddr = smem_u32(&KH[(n0 + nfi * 16 + lrow) * LDE + kb + lgrp * 8]);
            LDMATRIX_X4(bh4[0], bh4[1], bh4[2], bh4[3], bHaddr);
            uint32_t bLaddr = smem_u32(&KL[(n0 + nfi * 16 + lrow) * LDE + kb + lgrp * 8]);
            LDMATRIX_X4(bl4[0], bl4[1], bl4[2], bl4[3], bLaddr);

            // frag (2*nfi):   {bh4[0], bh4[2]} ; frag (2*nfi+1): {bh4[1], bh4[3]}
            uint32_t bh0[2] = {bh4[0], bh4[2]}, bh1[2] = {bh4[1], bh4[3]};
            uint32_t bl0[2] = {bl4[0], bl4[2]}, bl1[2] = {bl4[1], bl4[3]};

            #pragma unroll
            for (int mi = 0; mi < 2; mi++) {
                MMA_BF16(acc[mi][2 * nfi],     ah[mi], bh0);
                MMA_BF16(acc[mi][2 * nfi],     ah[mi], bl0);
                MMA_BF16(acc[mi][2 * nfi],     al[mi], bh0);
                MMA_BF16(acc[mi][2 * nfi + 1], ah[mi], bh1);
                MMA_BF16(acc[mi][2 * nfi + 1], ah[mi], bl1);
                MMA_BF16(acc[mi][2 * nfi + 1], al[mi], bh1);
            }
        }
    }

    // epilogue: write fp32 accumulators
    float* out = g_scores + (size_t)bh * SS * SS;
    const int g = lane >> 2, t2 = (lane & 3) * 2;
    #pragma unroll
    for (int mi = 0; mi < 2; mi++) {
        const int r1 = qt * 128 + m0 + mi * 16 + g;
        const int r2 = r1 + 8;
        #pragma unroll
        for (int nf = 0; nf < 8; nf++) {
            const int col = kt * 128 + n0 + nf * 8 + t2;
            *(float2*)&out[(size_t)r1 * SS + col] = make_float2(acc[mi][nf][0], acc[mi][nf][1]);
            *(float2*)&out[(size_t)r2 * SS + col] = make_float2(acc[mi][nf][2], acc[mi][nf][3]);
        }
    }
}

// ---------------------------------------------------------------------------
// Kernel 2: logits = conv2d(causal_mask(scores), W[h]) * scale
// ---------------------------------------------------------------------------
__global__ __launch_bounds__(256) void conv_kernel(const float* __restrict__ W)
{
    const int kt = blockIdx.x;
    const int qt = blockIdx.y;
    const int bh = blockIdx.z;
    const int k0 = kt * 128, q0 = qt * 32;
    if (k0 > q0 + 31) return;

    const float* Sb = g_scores + (size_t)bh * SS * SS;
    float* Lb = g_logits + (size_t)bh * SS * SS;

    __shared__ float sh[37][140];
    __shared__ float ws[66];

    const int tid = threadIdx.x;
    const int h = bh % NH;
    if (tid < 66) ws[tid] = W[h * 66 + tid];

    for (int i = tid; i < 37 * 138; i += 256) {
        int rr = i / 138, cc = i % 138;
        int q = q0 - 5 + rr;
        int k = k0 - 5 + cc;
        float v = 0.f;
        if (q >= 0 && k >= 0 && k <= q) v = Sb[(size_t)q * SS + k];
        sh[rr][cc] = v;
    }
    __syncthreads();

    const int r = tid / 8;
    const int c0 = (tid % 8) * 16;
    float out[16] = {};

    for (int dq = 0; dq < 6; dq++) {
        float win[26];
        #pragma unroll
        for (int t = 0; t < 26; t++) win[t] = sh[r + dq][c0 + t];
        #pragma unroll
        for (int dk = 0; dk < 11; dk++) {
            float w = ws[dq * 11 + dk];
            #pragma unroll
            for (int j = 0; j < 16; j++) out[j] += w * win[j + dk];
        }
    }

    const float scale = 0.088388347648318447f;
    const int q = q0 + r;
    #pragma unroll
    for (int j4 = 0; j4 < 4; j4++) {
        float4 o = make_float4(out[j4*4+0]*scale, out[j4*4+1]*scale,
                               out[j4*4+2]*scale, out[j4*4+3]*scale);
        *(float4*)&Lb[(size_t)q * SS + k0 + c0 + j4 * 4] = o;
    }
}

// ---------------------------------------------------------------------------
// Kernel 3: single-pass no-max softmax @ V (fp32 SIMT)
// ---------------------------------------------------------------------------
__global__ __launch_bounds__(256) void softmax_pv_kernel(
    const float* __restrict__ V, float* __restrict__ O)
{
    const int qt = blockIdx.x;
    const int bh = blockIdx.y;
    const int q0 = qt * 64;

    const float* Lb = g_logits + (size_t)bh * SS * SS;
    const float* Vb = V + (size_t)bh * SS * DD;
    float* Ob = O + (size_t)bh * SS * DD;

    const int tid = threadIdx.x;
    const int warp = tid >> 5, lane = tid & 31;

    __shared__ float Ps[64][33];
    __shared__ float Vs[32][132];
    __shared__ float rowSum[64];

    float psum[8] = {};
    const int r0 = (tid >> 4) * 4;
    const int d0 = (tid & 15) * 8;
    float acc[4][8] = {};

    const int nk = q0 + 64;

    for (int kc = 0; kc < nk; kc += 32) {
        for (int i = tid; i < 32 * 32; i += 256) {
            int kr = i >> 5, c4 = i & 31;
            *(float4*)&Vs[kr][c4 * 4] =
                *(const float4*)&Vb[(size_t)(kc + kr) * DD + c4 * 4];
        }
        const int kk = kc + lane;
        #pragma unroll
        for (int j = 0; j < 8; j++) {
            int r = warp + 8 * j;
            int qq = q0 + r;
            float e = 0.f;
            if (kk <= qq) e = fexp(Lb[(size_t)qq * SS + kk]);
            psum[j] += e;
            Ps[r][lane] = e;
        }
        __syncthreads();

        #pragma unroll
        for (int k2 = 0; k2 < 32; k2++) {
            float pv[4];
            #pragma unroll
            for (int i = 0; i < 4; i++) pv[i] = Ps[r0 + i][k2];
            float4 va = *(float4*)&Vs[k2][d0];
            float4 vb = *(float4*)&Vs[k2][d0 + 4];
            float vv[8] = {va.x, va.y, va.z, va.w, vb.x, vb.y, vb.z, vb.w};
            #pragma unroll
            for (int i = 0; i < 4; i++)
                #pragma unroll
                for (int j = 0; j < 8; j++)
                    acc[i][j] += pv[i] * vv[j];
        }
        __syncthreads();
    }

    #pragma unroll
    for (int j = 0; j < 8; j++) {
        float s = psum[j];
        #pragma unroll
        for (int o = 16; o; o >>= 1) s += __shfl_xor_sync(0xffffffffu, s, o);
        if (lane == 0) rowSum[warp + 8 * j] = s;
    }
    __syncthreads();

    #pragma unroll
    for (int i = 0; i < 4; i++) {
        int q = q0 + r0 + i;
        float inv = 1.f / rowSum[r0 + i];
        float* po = &Ob[(size_t)q * DD + d0];
        *(float4*)&po[0] = make_float4(acc[i][0]*inv, acc[i][1]*inv,
                                       acc[i][2]*inv, acc[i][3]*inv);
        *(float4*)&po[4] = make_float4(acc[i][4]*inv, acc[i][5]*inv,
                                       acc[i][6]*inv, acc[i][7]*inv);
    }
}

// ---------------------------------------------------------------------------
extern "C" void kernel_launch(void* const* d_in, const int* in_sizes, int n_in,
                              void* d_out, int out_size)
{
    const float* Q = (const float*)d_in[0];
    const float* K = (const float*)d_in[1];
    const float* V = (const float*)d_in[2];
    const float* W = (const float*)d_in[3];
    float* O = (float*)d_out;

    const int QK_SMEM = 4 * PLANE * (int)sizeof(__nv_bfloat16);  // 139264 B
    cudaFuncSetAttribute(qk_gemm_mma, cudaFuncAttributeMaxDynamicSharedMemorySize, QK_SMEM);

    dim3 g1(8, 8, NBH);
    qk_gemm_mma<<<g1, 256, QK_SMEM>>>(Q, K);

    dim3 g2(8, 32, NBH);
    conv_kernel<<<g2, 256>>>(W);

    dim3 g3(16, NBH);
    softmax_pv_kernel<<<g3, 256>>>(V, O);
}

// round 6
// speedup vs baseline: 4.9421x; 1.4878x over previous
#include <cuda_runtime.h>
#include <cuda_bf16.h>
#include <math.h>
#include <stdint.h>

#define SS 1024
#define DD 128
#define NBH 24
#define NH 12

// scratch planes: scores (raw QK^T, lower triangle only) and logits (conv*scale)
__device__ float g_scores[(size_t)NBH * SS * SS];
__device__ float g_logits[(size_t)NBH * SS * SS];

__device__ __forceinline__ uint32_t smem_u32(const void* p) {
    uint32_t a;
    asm("{ .reg .u64 t; cvta.to.shared.u64 t, %1; cvt.u32.u64 %0, t; }"
        : "=r"(a) : "l"(p));
    return a;
}

#define LDMATRIX_X4(r0, r1, r2, r3, addr) \
    asm volatile("ldmatrix.sync.aligned.m8n8.x4.shared.b16 {%0,%1,%2,%3}, [%4];" \
                 : "=r"(r0), "=r"(r1), "=r"(r2), "=r"(r3) : "r"(addr))

#define LDMATRIX_X4_T(r0, r1, r2, r3, addr) \
    asm volatile("ldmatrix.sync.aligned.m8n8.x4.trans.shared.b16 {%0,%1,%2,%3}, [%4];" \
                 : "=r"(r0), "=r"(r1), "=r"(r2), "=r"(r3) : "r"(addr))

#define MMA_BF16(d, a, b) \
    asm volatile("mma.sync.aligned.m16n8k16.row.col.f32.bf16.bf16.f32 " \
                 "{%0,%1,%2,%3}, {%4,%5,%6,%7}, {%8,%9}, {%0,%1,%2,%3};" \
                 : "+f"((d)[0]), "+f"((d)[1]), "+f"((d)[2]), "+f"((d)[3]) \
                 : "r"((a)[0]), "r"((a)[1]), "r"((a)[2]), "r"((a)[3]), \
                   "r"((b)[0]), "r"((b)[1]))

// fast exp on the FMA pipe
__device__ __forceinline__ float fexp(float x) {
    float y = x * 1.4426950408889634f;
    y = fminf(fmaxf(y, -120.f), 120.f);
    float fy = floorf(y);
    float f = y - fy;
    float p = 1.5403530e-4f;
    p = fmaf(p, f, 1.3333558e-3f);
    p = fmaf(p, f, 9.6181291e-3f);
    p = fmaf(p, f, 5.5504109e-2f);
    p = fmaf(p, f, 2.4022651e-1f);
    p = fmaf(p, f, 6.9314718e-1f);
    p = fmaf(p, f, 1.0f);
    int e = (int)fy;
    return p * __int_as_float((e + 127) << 23);
}

__device__ __forceinline__ void split_store4(__nv_bfloat16* hi, __nv_bfloat16* lo, float4 v) {
    __nv_bfloat16 h0 = __float2bfloat16(v.x), h1 = __float2bfloat16(v.y);
    __nv_bfloat16 h2 = __float2bfloat16(v.z), h3 = __float2bfloat16(v.w);
    __nv_bfloat162 hp0(h0, h1), hp1(h2, h3);
    __nv_bfloat162 lp0 = __floats2bfloat162_rn(v.x - __bfloat162float(h0),
                                               v.y - __bfloat162float(h1));
    __nv_bfloat162 lp1 = __floats2bfloat162_rn(v.z - __bfloat162float(h2),
                                               v.w - __bfloat162float(h3));
    *(uint2*)hi = make_uint2(*(uint32_t*)&hp0, *(uint32_t*)&hp1);
    *(uint2*)lo = make_uint2(*(uint32_t*)&lp0, *(uint32_t*)&lp1);
}

// ---------------------------------------------------------------------------
// Kernel 1: scores = Q @ K^T via mma.sync bf16 split (3 terms), two 64-col
// K-halves staged serially to halve smem (73.7KB -> 2 CTAs/SM).
// ---------------------------------------------------------------------------
#define LDE2 72
#define PLANE2 (128 * LDE2)

__global__ __launch_bounds__(256) void qk_gemm_mma(
    const float* __restrict__ Q, const float* __restrict__ K)
{
    const int kt = blockIdx.x;
    const int qt = blockIdx.y;
    if (kt > qt) return;
    const int bh = blockIdx.z;

    extern __shared__ __align__(16) __nv_bfloat16 smem[];
    __nv_bfloat16* QH = smem;
    __nv_bfloat16* QL = smem + PLANE2;
    __nv_bfloat16* KH = smem + 2 * PLANE2;
    __nv_bfloat16* KL = smem + 3 * PLANE2;

    const int tid = threadIdx.x;
    const float* Qb = Q + ((size_t)bh * SS + (size_t)qt * 128) * DD;
    const float* Kb = K + ((size_t)bh * SS + (size_t)kt * 128) * DD;

    const int warp = tid >> 5, lane = tid & 31;
    const int m0 = (warp & 3) * 32;
    const int n0 = (warp >> 2) * 64;
    const int lrow = lane & 15;
    const int lgrp = lane >> 4;

    float acc[2][8][4] = {};

    for (int half = 0; half < 2; half++) {
        if (half) __syncthreads();
        // stage 128 rows x 64 cols of Q,K -> hi/lo planes
        for (int i = tid; i < 128 * 16; i += 256) {
            const int row = i >> 4, k = (i & 15) * 4;
            float4 v = *(const float4*)&Qb[(size_t)row * DD + half * 64 + k];
            split_store4(&QH[row * LDE2 + k], &QL[row * LDE2 + k], v);
            float4 u = *(const float4*)&Kb[(size_t)row * DD + half * 64 + k];
            split_store4(&KH[row * LDE2 + k], &KL[row * LDE2 + k], u);
        }
        __syncthreads();

        #pragma unroll
        for (int ks = 0; ks < 4; ks++) {
            const int kb = ks * 16;
            uint32_t ah[2][4], al[2][4];
            #pragma unroll
            for (int mi = 0; mi < 2; mi++) {
                uint32_t aH = smem_u32(&QH[(m0 + mi * 16 + lrow) * LDE2 + kb + lgrp * 8]);
                LDMATRIX_X4(ah[mi][0], ah[mi][1], ah[mi][2], ah[mi][3], aH);
                uint32_t aL = smem_u32(&QL[(m0 + mi * 16 + lrow) * LDE2 + kb + lgrp * 8]);
                LDMATRIX_X4(al[mi][0], al[mi][1], al[mi][2], al[mi][3], aL);
            }
            #pragma unroll
            for (int nfi = 0; nfi < 4; nfi++) {
                uint32_t bh4[4], bl4[4];
                uint32_t bHaddr = smem_u32(&KH[(n0 + nfi * 16 + lrow) * LDE2 + kb + lgrp * 8]);
                LDMATRIX_X4(bh4[0], bh4[1], bh4[2], bh4[3], bHaddr);
                uint32_t bLaddr = smem_u32(&KL[(n0 + nfi * 16 + lrow) * LDE2 + kb + lgrp * 8]);
                LDMATRIX_X4(bl4[0], bl4[1], bl4[2], bl4[3], bLaddr);

                uint32_t bh0[2] = {bh4[0], bh4[2]}, bh1[2] = {bh4[1], bh4[3]};
                uint32_t bl0[2] = {bl4[0], bl4[2]}, bl1[2] = {bl4[1], bl4[3]};

                #pragma unroll
                for (int mi = 0; mi < 2; mi++) {
                    MMA_BF16(acc[mi][2 * nfi],     ah[mi], bh0);
                    MMA_BF16(acc[mi][2 * nfi],     ah[mi], bl0);
                    MMA_BF16(acc[mi][2 * nfi],     al[mi], bh0);
                    MMA_BF16(acc[mi][2 * nfi + 1], ah[mi], bh1);
                    MMA_BF16(acc[mi][2 * nfi + 1], ah[mi], bl1);
                    MMA_BF16(acc[mi][2 * nfi + 1], al[mi], bh1);
                }
            }
        }
    }

    float* out = g_scores + (size_t)bh * SS * SS;
    const int g = lane >> 2, t2 = (lane & 3) * 2;
    #pragma unroll
    for (int mi = 0; mi < 2; mi++) {
        const int r1 = qt * 128 + m0 + mi * 16 + g;
        const int r2 = r1 + 8;
        #pragma unroll
        for (int nf = 0; nf < 8; nf++) {
            const int col = kt * 128 + n0 + nf * 8 + t2;
            *(float2*)&out[(size_t)r1 * SS + col] = make_float2(acc[mi][nf][0], acc[mi][nf][1]);
            *(float2*)&out[(size_t)r2 * SS + col] = make_float2(acc[mi][nf][2], acc[mi][nf][3]);
        }
    }
}

// ---------------------------------------------------------------------------
// Kernel 2: logits = conv2d(causal_mask(scores), W[h]) * scale
// ---------------------------------------------------------------------------
__global__ __launch_bounds__(256) void conv_kernel(const float* __restrict__ W)
{
    const int kt = blockIdx.x;
    const int qt = blockIdx.y;
    const int bh = blockIdx.z;
    const int k0 = kt * 128, q0 = qt * 32;
    if (k0 > q0 + 31) return;

    const float* Sb = g_scores + (size_t)bh * SS * SS;
    float* Lb = g_logits + (size_t)bh * SS * SS;

    __shared__ float sh[37][140];
    __shared__ float ws[66];

    const int tid = threadIdx.x;
    const int h = bh % NH;
    if (tid < 66) ws[tid] = W[h * 66 + tid];

    for (int i = tid; i < 37 * 138; i += 256) {
        int rr = i / 138, cc = i % 138;
        int q = q0 - 5 + rr;
        int k = k0 - 5 + cc;
        float v = 0.f;
        if (q >= 0 && k >= 0 && k <= q) v = Sb[(size_t)q * SS + k];
        sh[rr][cc] = v;
    }
    __syncthreads();

    const int r = tid / 8;
    const int c0 = (tid % 8) * 16;
    float out[16] = {};

    for (int dq = 0; dq < 6; dq++) {
        float win[26];
        #pragma unroll
        for (int t = 0; t < 26; t++) win[t] = sh[r + dq][c0 + t];
        #pragma unroll
        for (int dk = 0; dk < 11; dk++) {
            float w = ws[dq * 11 + dk];
            #pragma unroll
            for (int j = 0; j < 16; j++) out[j] += w * win[j + dk];
        }
    }

    const float scale = 0.088388347648318447f;
    const int q = q0 + r;
    #pragma unroll
    for (int j4 = 0; j4 < 4; j4++) {
        float4 o = make_float4(out[j4*4+0]*scale, out[j4*4+1]*scale,
                               out[j4*4+2]*scale, out[j4*4+3]*scale);
        *(float4*)&Lb[(size_t)q * SS + k0 + c0 + j4 * 4] = o;
    }
}

// ---------------------------------------------------------------------------
// Kernel 3: single-pass no-max softmax @ V via mma.sync (split-bf16 P and V).
// O = (P @ V) / rowSum,  P = exp(logits),  O ~= Phi*Vhi + Phi*Vlo + Plo*Vhi.
// Block: 64 q-rows x 128 d, 8 warps (2 m x 4 n), 64-key chunks.
// ---------------------------------------------------------------------------
#define PV_LDP 72    // P plane stride (bf16)
#define PV_LDV 136   // V plane stride (bf16)

__global__ __launch_bounds__(256) void softmax_pv_mma(
    const float* __restrict__ V, float* __restrict__ O)
{
    const int qt = blockIdx.x;    // 0..15
    const int bh = blockIdx.y;
    const int q0 = qt * 64;

    const float* Lb = g_logits + (size_t)bh * SS * SS;
    const float* Vb = V + (size_t)bh * SS * DD;
    float* Ob = O + (size_t)bh * SS * DD;

    extern __shared__ __align__(16) char dsm[];
    __nv_bfloat16* Ph = (__nv_bfloat16*)dsm;            // 64 x 72
    __nv_bfloat16* Pl = Ph + 64 * PV_LDP;
    __nv_bfloat16* Vh = Pl + 64 * PV_LDP;               // 64 x 136
    __nv_bfloat16* Vl = Vh + 64 * PV_LDV;
    float* rowSum = (float*)(Vl + 64 * PV_LDV);         // 64

    const int tid = threadIdx.x;
    const int warp = tid >> 5, lane = tid & 31;
    const int m0 = (warp & 1) * 32;
    const int n0 = (warp >> 1) * 32;

    // P staging mapping: fixed row per thread across chunks
    const int pr = tid >> 2;            // 0..63
    const int pc = (tid & 3) * 16;      // 0..48
    const int pq = q0 + pr;
    float psum = 0.f;

    float acc[2][4][4] = {};            // [mi][n8-block][4]

    const int lrow = lane & 15;
    const int lgrp = lane >> 4;
    const int bi = lane >> 3;           // trans-matrix id
    const int brow = lane & 7;

    for (int kc = 0; kc < q0 + 64; kc += 64) {
        if (kc) __syncthreads();
        // stage V chunk 64 x 128 -> hi/lo
        for (int i = tid; i < 64 * 32; i += 256) {
            const int kr = i >> 5, c = (i & 31) * 4;
            float4 v = *(const float4*)&Vb[(size_t)(kc + kr) * DD + c];
            split_store4(&Vh[kr * PV_LDV + c], &Vl[kr * PV_LDV + c], v);
        }
        // stage P = exp(logit) (masked), accumulate row partial sums
        {
            const float* Lrow = &Lb[(size_t)pq * SS + kc + pc];
            #pragma unroll
            for (int j4 = 0; j4 < 4; j4++) {
                float4 l = *(const float4*)&Lrow[j4 * 4];
                const int kbase = kc + pc + j4 * 4;
                float e0 = (kbase + 0 <= pq) ? fexp(l.x) : 0.f;
                float e1 = (kbase + 1 <= pq) ? fexp(l.y) : 0.f;
                float e2 = (kbase + 2 <= pq) ? fexp(l.z) : 0.f;
                float e3 = (kbase + 3 <= pq) ? fexp(l.w) : 0.f;
                psum += (e0 + e1) + (e2 + e3);
                split_store4(&Ph[pr * PV_LDP + pc + j4 * 4],
                             &Pl[pr * PV_LDP + pc + j4 * 4],
                             make_float4(e0, e1, e2, e3));
            }
        }
        __syncthreads();

        #pragma unroll
        for (int ks = 0; ks < 4; ks++) {
            const int kb = ks * 16;
            uint32_t ah[2][4], al[2][4];
            #pragma unroll
            for (int mi = 0; mi < 2; mi++) {
                uint32_t aH = smem_u32(&Ph[(m0 + mi * 16 + lrow) * PV_LDP + kb + lgrp * 8]);
                LDMATRIX_X4(ah[mi][0], ah[mi][1], ah[mi][2], ah[mi][3], aH);
                uint32_t aL = smem_u32(&Pl[(m0 + mi * 16 + lrow) * PV_LDP + kb + lgrp * 8]);
                LDMATRIX_X4(al[mi][0], al[mi][1], al[mi][2], al[mi][3], aL);
            }
            #pragma unroll
            for (int ng = 0; ng < 2; ng++) {
                // V trans load: [k][n] smem, address rows = k
                const int vrow = kb + (bi & 1) * 8 + brow;
                const int vcol = n0 + ng * 16 + (bi >> 1) * 8;
                uint32_t bh4[4], bl4[4];
                uint32_t bHaddr = smem_u32(&Vh[vrow * PV_LDV + vcol]);
                LDMATRIX_X4_T(bh4[0], bh4[1], bh4[2], bh4[3], bHaddr);
                uint32_t bLaddr = smem_u32(&Vl[vrow * PV_LDV + vcol]);
                LDMATRIX_X4_T(bl4[0], bl4[1], bl4[2], bl4[3], bLaddr);

                uint32_t bh0[2] = {bh4[0], bh4[1]}, bh1[2] = {bh4[2], bh4[3]};
                uint32_t bl0[2] = {bl4[0], bl4[1]}, bl1[2] = {bl4[2], bl4[3]};

                #pragma unroll
                for (int mi = 0; mi < 2; mi++) {
                    MMA_BF16(acc[mi][2 * ng],     ah[mi], bh0);
                    MMA_BF16(acc[mi][2 * ng],     ah[mi], bl0);
                    MMA_BF16(acc[mi][2 * ng],     al[mi], bh0);
                    MMA_BF16(acc[mi][2 * ng + 1], ah[mi], bh1);
                    MMA_BF16(acc[mi][2 * ng + 1], ah[mi], bl1);
                    MMA_BF16(acc[mi][2 * ng + 1], al[mi], bh1);
                }
            }
        }
    }

    // finalize row sums (quad reduce; quad lanes share row pr)
    psum += __shfl_xor_sync(0xffffffffu, psum, 1);
    psum += __shfl_xor_sync(0xffffffffu, psum, 2);
    if ((tid & 3) == 0) rowSum[pr] = psum;
    __syncthreads();

    // epilogue: normalize and store
    const int g = lane >> 2, t2 = (lane & 3) * 2;
    #pragma unroll
    for (int mi = 0; mi < 2; mi++) {
        const int lr1 = m0 + mi * 16 + g;
        const int lr2 = lr1 + 8;
        const float inv1 = 1.f / rowSum[lr1];
        const float inv2 = 1.f / rowSum[lr2];
        #pragma unroll
        for (int nf = 0; nf < 4; nf++) {
            const int col = n0 + nf * 8 + t2;
            *(float2*)&Ob[(size_t)(q0 + lr1) * DD + col] =
                make_float2(acc[mi][nf][0] * inv1, acc[mi][nf][1] * inv1);
            *(float2*)&Ob[(size_t)(q0 + lr2) * DD + col] =
                make_float2(acc[mi][nf][2] * inv2, acc[mi][nf][3] * inv2);
        }
    }
}

// ---------------------------------------------------------------------------
extern "C" void kernel_launch(void* const* d_in, const int* in_sizes, int n_in,
                              void* d_out, int out_size)
{
    const float* Q = (const float*)d_in[0];
    const float* K = (const float*)d_in[1];
    const float* V = (const float*)d_in[2];
    const float* W = (const float*)d_in[3];
    float* O = (float*)d_out;

    const int QK_SMEM = 4 * PLANE2 * (int)sizeof(__nv_bfloat16);  // 73728 B
    cudaFuncSetAttribute(qk_gemm_mma, cudaFuncAttributeMaxDynamicSharedMemorySize, QK_SMEM);

    const int PV_SMEM = (2 * 64 * PV_LDP + 2 * 64 * PV_LDV) * (int)sizeof(__nv_bfloat16)
                        + 64 * (int)sizeof(float);                // 53504 B
    cudaFuncSetAttribute(softmax_pv_mma, cudaFuncAttributeMaxDynamicSharedMemorySize, PV_SMEM);

    dim3 g1(8, 8, NBH);
    qk_gemm_mma<<<g1, 256, QK_SMEM>>>(Q, K);

    dim3 g2(8, 32, NBH);
    conv_kernel<<<g2, 256>>>(W);

    dim3 g3(16, NBH);
    softmax_pv_mma<<<g3, 256, PV_SMEM>>>(V, O);
}

// round 7
// speedup vs baseline: 5.5187x; 1.1167x over previous
#include <cuda_runtime.h>
#include <cuda_bf16.h>
#include <math.h>
#include <stdint.h>

#define SS 1024
#define DD 128
#define NBH 24
#define NH 12

// scratch planes: scores (raw QK^T, lower triangle only) and logits (conv*scale)
__device__ float g_scores[(size_t)NBH * SS * SS];
__device__ float g_logits[(size_t)NBH * SS * SS];

__device__ __forceinline__ uint32_t smem_u32(const void* p) {
    uint32_t a;
    asm("{ .reg .u64 t; cvta.to.shared.u64 t, %1; cvt.u32.u64 %0, t; }"
        : "=r"(a) : "l"(p));
    return a;
}

#define LDMATRIX_X4(r0, r1, r2, r3, addr) \
    asm volatile("ldmatrix.sync.aligned.m8n8.x4.shared.b16 {%0,%1,%2,%3}, [%4];" \
                 : "=r"(r0), "=r"(r1), "=r"(r2), "=r"(r3) : "r"(addr))

#define LDMATRIX_X4_T(r0, r1, r2, r3, addr) \
    asm volatile("ldmatrix.sync.aligned.m8n8.x4.trans.shared.b16 {%0,%1,%2,%3}, [%4];" \
                 : "=r"(r0), "=r"(r1), "=r"(r2), "=r"(r3) : "r"(addr))

#define MMA_BF16(d, a, b) \
    asm volatile("mma.sync.aligned.m16n8k16.row.col.f32.bf16.bf16.f32 " \
                 "{%0,%1,%2,%3}, {%4,%5,%6,%7}, {%8,%9}, {%0,%1,%2,%3};" \
                 : "+f"((d)[0]), "+f"((d)[1]), "+f"((d)[2]), "+f"((d)[3]) \
                 : "r"((a)[0]), "r"((a)[1]), "r"((a)[2]), "r"((a)[3]), \
                   "r"((b)[0]), "r"((b)[1]))

// fast exp on the FMA pipe
__device__ __forceinline__ float fexp(float x) {
    float y = x * 1.4426950408889634f;
    y = fminf(fmaxf(y, -120.f), 120.f);
    float fy = floorf(y);
    float f = y - fy;
    float p = 1.5403530e-4f;
    p = fmaf(p, f, 1.3333558e-3f);
    p = fmaf(p, f, 9.6181291e-3f);
    p = fmaf(p, f, 5.5504109e-2f);
    p = fmaf(p, f, 2.4022651e-1f);
    p = fmaf(p, f, 6.9314718e-1f);
    p = fmaf(p, f, 1.0f);
    int e = (int)fy;
    return p * __int_as_float((e + 127) << 23);
}

__device__ __forceinline__ void split_store4(__nv_bfloat16* hi, __nv_bfloat16* lo, float4 v) {
    __nv_bfloat16 h0 = __float2bfloat16(v.x), h1 = __float2bfloat16(v.y);
    __nv_bfloat16 h2 = __float2bfloat16(v.z), h3 = __float2bfloat16(v.w);
    __nv_bfloat162 hp0(h0, h1), hp1(h2, h3);
    __nv_bfloat162 lp0 = __floats2bfloat162_rn(v.x - __bfloat162float(h0),
                                               v.y - __bfloat162float(h1));
    __nv_bfloat162 lp1 = __floats2bfloat162_rn(v.z - __bfloat162float(h2),
                                               v.w - __bfloat162float(h3));
    *(uint2*)hi = make_uint2(*(uint32_t*)&hp0, *(uint32_t*)&hp1);
    *(uint2*)lo = make_uint2(*(uint32_t*)&lp0, *(uint32_t*)&lp1);
}

// ---------------------------------------------------------------------------
// Kernel 1: scores = Q @ K^T via mma.sync bf16 split (3 terms), two 64-col
// K-halves staged serially. __launch_bounds__(256,2) caps regs at 128 so two
// CTAs/SM actually fit (smem 73.7KB x2 = 147KB < 228KB).
// ---------------------------------------------------------------------------
#define LDE2 72
#define PLANE2 (128 * LDE2)

__global__ __launch_bounds__(256, 2) void qk_gemm_mma(
    const float* __restrict__ Q, const float* __restrict__ K)
{
    const int kt = blockIdx.x;
    const int qt = blockIdx.y;
    if (kt > qt) return;
    const int bh = blockIdx.z;

    extern __shared__ __align__(16) __nv_bfloat16 smem[];
    __nv_bfloat16* QH = smem;
    __nv_bfloat16* QL = smem + PLANE2;
    __nv_bfloat16* KH = smem + 2 * PLANE2;
    __nv_bfloat16* KL = smem + 3 * PLANE2;

    const int tid = threadIdx.x;
    const float* Qb = Q + ((size_t)bh * SS + (size_t)qt * 128) * DD;
    const float* Kb = K + ((size_t)bh * SS + (size_t)kt * 128) * DD;

    const int warp = tid >> 5, lane = tid & 31;
    const int m0 = (warp & 3) * 32;
    const int n0 = (warp >> 2) * 64;
    const int lrow = lane & 15;
    const int lgrp = lane >> 4;

    float acc[2][8][4] = {};

    for (int half = 0; half < 2; half++) {
        if (half) __syncthreads();
        for (int i = tid; i < 128 * 16; i += 256) {
            const int row = i >> 4, k = (i & 15) * 4;
            float4 v = *(const float4*)&Qb[(size_t)row * DD + half * 64 + k];
            split_store4(&QH[row * LDE2 + k], &QL[row * LDE2 + k], v);
            float4 u = *(const float4*)&Kb[(size_t)row * DD + half * 64 + k];
            split_store4(&KH[row * LDE2 + k], &KL[row * LDE2 + k], u);
        }
        __syncthreads();

        #pragma unroll
        for (int ks = 0; ks < 4; ks++) {
            const int kb = ks * 16;
            uint32_t ah[2][4], al[2][4];
            #pragma unroll
            for (int mi = 0; mi < 2; mi++) {
                uint32_t aH = smem_u32(&QH[(m0 + mi * 16 + lrow) * LDE2 + kb + lgrp * 8]);
                LDMATRIX_X4(ah[mi][0], ah[mi][1], ah[mi][2], ah[mi][3], aH);
                uint32_t aL = smem_u32(&QL[(m0 + mi * 16 + lrow) * LDE2 + kb + lgrp * 8]);
                LDMATRIX_X4(al[mi][0], al[mi][1], al[mi][2], al[mi][3], aL);
            }
            #pragma unroll
            for (int nfi = 0; nfi < 4; nfi++) {
                uint32_t bh4[4], bl4[4];
                uint32_t bHaddr = smem_u32(&KH[(n0 + nfi * 16 + lrow) * LDE2 + kb + lgrp * 8]);
                LDMATRIX_X4(bh4[0], bh4[1], bh4[2], bh4[3], bHaddr);
                uint32_t bLaddr = smem_u32(&KL[(n0 + nfi * 16 + lrow) * LDE2 + kb + lgrp * 8]);
                LDMATRIX_X4(bl4[0], bl4[1], bl4[2], bl4[3], bLaddr);

                uint32_t bh0[2] = {bh4[0], bh4[2]}, bh1[2] = {bh4[1], bh4[3]};
                uint32_t bl0[2] = {bl4[0], bl4[2]}, bl1[2] = {bl4[1], bl4[3]};

                #pragma unroll
                for (int mi = 0; mi < 2; mi++) {
                    MMA_BF16(acc[mi][2 * nfi],     ah[mi], bh0);
                    MMA_BF16(acc[mi][2 * nfi],     ah[mi], bl0);
                    MMA_BF16(acc[mi][2 * nfi],     al[mi], bh0);
                    MMA_BF16(acc[mi][2 * nfi + 1], ah[mi], bh1);
                    MMA_BF16(acc[mi][2 * nfi + 1], ah[mi], bl1);
                    MMA_BF16(acc[mi][2 * nfi + 1], al[mi], bh1);
                }
            }
        }
    }

    float* out = g_scores + (size_t)bh * SS * SS;
    const int g = lane >> 2, t2 = (lane & 3) * 2;
    #pragma unroll
    for (int mi = 0; mi < 2; mi++) {
        const int r1 = qt * 128 + m0 + mi * 16 + g;
        const int r2 = r1 + 8;
        #pragma unroll
        for (int nf = 0; nf < 8; nf++) {
            const int col = kt * 128 + n0 + nf * 8 + t2;
            *(float2*)&out[(size_t)r1 * SS + col] = make_float2(acc[mi][nf][0], acc[mi][nf][1]);
            *(float2*)&out[(size_t)r2 * SS + col] = make_float2(acc[mi][nf][2], acc[mi][nf][3]);
        }
    }
}

// ---------------------------------------------------------------------------
// Kernel 2: logits = conv2d(causal_mask(scores), W[h]) * scale
// Window loads via float4 (fewer LDS transactions / conflicts).
// ---------------------------------------------------------------------------
__global__ __launch_bounds__(256) void conv_kernel(const float* __restrict__ W)
{
    const int kt = blockIdx.x;
    const int qt = blockIdx.y;
    const int bh = blockIdx.z;
    const int k0 = kt * 128, q0 = qt * 32;
    if (k0 > q0 + 31) return;

    const float* Sb = g_scores + (size_t)bh * SS * SS;
    float* Lb = g_logits + (size_t)bh * SS * SS;

    __shared__ __align__(16) float sh[37][140];
    __shared__ float ws[66];

    const int tid = threadIdx.x;
    const int h = bh % NH;
    if (tid < 66) ws[tid] = W[h * 66 + tid];

    for (int i = tid; i < 37 * 138; i += 256) {
        int rr = i / 138, cc = i % 138;
        int q = q0 - 5 + rr;
        int k = k0 - 5 + cc;
        float v = 0.f;
        if (q >= 0 && k >= 0 && k <= q) v = Sb[(size_t)q * SS + k];
        sh[rr][cc] = v;
    }
    __syncthreads();

    const int r = tid / 8;
    const int c0 = (tid % 8) * 16;
    float out[16] = {};

    for (int dq = 0; dq < 6; dq++) {
        float win[28];
        #pragma unroll
        for (int t4 = 0; t4 < 7; t4++)
            *(float4*)&win[t4 * 4] = *(float4*)&sh[r + dq][c0 + t4 * 4];
        #pragma unroll
        for (int dk = 0; dk < 11; dk++) {
            float w = ws[dq * 11 + dk];
            #pragma unroll
            for (int j = 0; j < 16; j++) out[j] += w * win[j + dk];
        }
    }

    const float scale = 0.088388347648318447f;
    const int q = q0 + r;
    #pragma unroll
    for (int j4 = 0; j4 < 4; j4++) {
        float4 o = make_float4(out[j4*4+0]*scale, out[j4*4+1]*scale,
                               out[j4*4+2]*scale, out[j4*4+3]*scale);
        *(float4*)&Lb[(size_t)q * SS + k0 + c0 + j4 * 4] = o;
    }
}

// ---------------------------------------------------------------------------
// Kernel 3: single-pass no-max softmax @ V via mma.sync (split-bf16 P and V).
// __launch_bounds__(256,2) for 2 CTAs/SM (smem 53.5KB x2 fits).
// ---------------------------------------------------------------------------
#define PV_LDP 72    // P plane stride (bf16)
#define PV_LDV 136   // V plane stride (bf16)

__global__ __launch_bounds__(256, 2) void softmax_pv_mma(
    const float* __restrict__ V, float* __restrict__ O)
{
    const int qt = blockIdx.x;    // 0..15
    const int bh = blockIdx.y;
    const int q0 = qt * 64;

    const float* Lb = g_logits + (size_t)bh * SS * SS;
    const float* Vb = V + (size_t)bh * SS * DD;
    float* Ob = O + (size_t)bh * SS * DD;

    extern __shared__ __align__(16) char dsm[];
    __nv_bfloat16* Ph = (__nv_bfloat16*)dsm;            // 64 x 72
    __nv_bfloat16* Pl = Ph + 64 * PV_LDP;
    __nv_bfloat16* Vh = Pl + 64 * PV_LDP;               // 64 x 136
    __nv_bfloat16* Vl = Vh + 64 * PV_LDV;
    float* rowSum = (float*)(Vl + 64 * PV_LDV);         // 64

    const int tid = threadIdx.x;
    const int warp = tid >> 5, lane = tid & 31;
    const int m0 = (warp & 1) * 32;
    const int n0 = (warp >> 1) * 32;

    const int pr = tid >> 2;            // 0..63
    const int pc = (tid & 3) * 16;      // 0..48
    const int pq = q0 + pr;
    float psum = 0.f;

    float acc[2][4][4] = {};

    const int lrow = lane & 15;
    const int lgrp = lane >> 4;
    const int bi = lane >> 3;
    const int brow = lane & 7;

    for (int kc = 0; kc < q0 + 64; kc += 64) {
        if (kc) __syncthreads();
        for (int i = tid; i < 64 * 32; i += 256) {
            const int kr = i >> 5, c = (i & 31) * 4;
            float4 v = *(const float4*)&Vb[(size_t)(kc + kr) * DD + c];
            split_store4(&Vh[kr * PV_LDV + c], &Vl[kr * PV_LDV + c], v);
        }
        {
            const float* Lrow = &Lb[(size_t)pq * SS + kc + pc];
            #pragma unroll
            for (int j4 = 0; j4 < 4; j4++) {
                float4 l = *(const float4*)&Lrow[j4 * 4];
                const int kbase = kc + pc + j4 * 4;
                float e0 = (kbase + 0 <= pq) ? fexp(l.x) : 0.f;
                float e1 = (kbase + 1 <= pq) ? fexp(l.y) : 0.f;
                float e2 = (kbase + 2 <= pq) ? fexp(l.z) : 0.f;
                float e3 = (kbase + 3 <= pq) ? fexp(l.w) : 0.f;
                psum += (e0 + e1) + (e2 + e3);
                split_store4(&Ph[pr * PV_LDP + pc + j4 * 4],
                             &Pl[pr * PV_LDP + pc + j4 * 4],
                             make_float4(e0, e1, e2, e3));
            }
        }
        __syncthreads();

        #pragma unroll
        for (int ks = 0; ks < 4; ks++) {
            const int kb = ks * 16;
            uint32_t ah[2][4], al[2][4];
            #pragma unroll
            for (int mi = 0; mi < 2; mi++) {
                uint32_t aH = smem_u32(&Ph[(m0 + mi * 16 + lrow) * PV_LDP + kb + lgrp * 8]);
                LDMATRIX_X4(ah[mi][0], ah[mi][1], ah[mi][2], ah[mi][3], aH);
                uint32_t aL = smem_u32(&Pl[(m0 + mi * 16 + lrow) * PV_LDP + kb + lgrp * 8]);
                LDMATRIX_X4(al[mi][0], al[mi][1], al[mi][2], al[mi][3], aL);
            }
            #pragma unroll
            for (int ng = 0; ng < 2; ng++) {
                const int vrow = kb + (bi & 1) * 8 + brow;
                const int vcol = n0 + ng * 16 + (bi >> 1) * 8;
                uint32_t bh4[4], bl4[4];
                uint32_t bHaddr = smem_u32(&Vh[vrow * PV_LDV + vcol]);
                LDMATRIX_X4_T(bh4[0], bh4[1], bh4[2], bh4[3], bHaddr);
                uint32_t bLaddr = smem_u32(&Vl[vrow * PV_LDV + vcol]);
                LDMATRIX_X4_T(bl4[0], bl4[1], bl4[2], bl4[3], bLaddr);

                uint32_t bh0[2] = {bh4[0], bh4[1]}, bh1[2] = {bh4[2], bh4[3]};
                uint32_t bl0[2] = {bl4[0], bl4[1]}, bl1[2] = {bl4[2], bl4[3]};

                #pragma unroll
                for (int mi = 0; mi < 2; mi++) {
                    MMA_BF16(acc[mi][2 * ng],     ah[mi], bh0);
                    MMA_BF16(acc[mi][2 * ng],     ah[mi], bl0);
                    MMA_BF16(acc[mi][2 * ng],     al[mi], bh0);
                    MMA_BF16(acc[mi][2 * ng + 1], ah[mi], bh1);
                    MMA_BF16(acc[mi][2 * ng + 1], ah[mi], bl1);
                    MMA_BF16(acc[mi][2 * ng + 1], al[mi], bh1);
                }
            }
        }
    }

    psum += __shfl_xor_sync(0xffffffffu, psum, 1);
    psum += __shfl_xor_sync(0xffffffffu, psum, 2);
    if ((tid & 3) == 0) rowSum[pr] = psum;
    __syncthreads();

    const int g = lane >> 2, t2 = (lane & 3) * 2;
    #pragma unroll
    for (int mi = 0; mi < 2; mi++) {
        const int lr1 = m0 + mi * 16 + g;
        const int lr2 = lr1 + 8;
        const float inv1 = 1.f / rowSum[lr1];
        const float inv2 = 1.f / rowSum[lr2];
        #pragma unroll
        for (int nf = 0; nf < 4; nf++) {
            const int col = n0 + nf * 8 + t2;
            *(float2*)&Ob[(size_t)(q0 + lr1) * DD + col] =
                make_float2(acc[mi][nf][0] * inv1, acc[mi][nf][1] * inv1);
            *(float2*)&Ob[(size_t)(q0 + lr2) * DD + col] =
                make_float2(acc[mi][nf][2] * inv2, acc[mi][nf][3] * inv2);
        }
    }
}

// ---------------------------------------------------------------------------
extern "C" void kernel_launch(void* const* d_in, const int* in_sizes, int n_in,
                              void* d_out, int out_size)
{
    const float* Q = (const float*)d_in[0];
    const float* K = (const float*)d_in[1];
    const float* V = (const float*)d_in[2];
    const float* W = (const float*)d_in[3];
    float* O = (float*)d_out;

    const int QK_SMEM = 4 * PLANE2 * (int)sizeof(__nv_bfloat16);  // 73728 B
    cudaFuncSetAttribute(qk_gemm_mma, cudaFuncAttributeMaxDynamicSharedMemorySize, QK_SMEM);

    const int PV_SMEM = (2 * 64 * PV_LDP + 2 * 64 * PV_LDV) * (int)sizeof(__nv_bfloat16)
                        + 64 * (int)sizeof(float);                // 53504 B
    cudaFuncSetAttribute(softmax_pv_mma, cudaFuncAttributeMaxDynamicSharedMemorySize, PV_SMEM);

    dim3 g1(8, 8, NBH);
    qk_gemm_mma<<<g1, 256, QK_SMEM>>>(Q, K);

    dim3 g2(8, 32, NBH);
    conv_kernel<<<g2, 256>>>(W);

    dim3 g3(16, NBH);
    softmax_pv_mma<<<g3, 256, PV_SMEM>>>(V, O);
}

// round 8
// speedup vs baseline: 6.0239x; 1.0915x over previous
#include <cuda_runtime.h>
#include <cuda_bf16.h>
#include <math.h>
#include <stdint.h>

#define SS 1024
#define DD 128
#define NBH 24
#define NH 12

// scratch: scores (raw QK^T, lower-triangle tiles only)
__device__ float g_scores[(size_t)NBH * SS * SS];

__device__ __forceinline__ uint32_t smem_u32(const void* p) {
    uint32_t a;
    asm("{ .reg .u64 t; cvta.to.shared.u64 t, %1; cvt.u32.u64 %0, t; }"
        : "=r"(a) : "l"(p));
    return a;
}

#define LDMATRIX_X4(r0, r1, r2, r3, addr) \
    asm volatile("ldmatrix.sync.aligned.m8n8.x4.shared.b16 {%0,%1,%2,%3}, [%4];" \
                 : "=r"(r0), "=r"(r1), "=r"(r2), "=r"(r3) : "r"(addr))

#define LDMATRIX_X4_T(r0, r1, r2, r3, addr) \
    asm volatile("ldmatrix.sync.aligned.m8n8.x4.trans.shared.b16 {%0,%1,%2,%3}, [%4];" \
                 : "=r"(r0), "=r"(r1), "=r"(r2), "=r"(r3) : "r"(addr))

#define MMA_BF16(d, a, b) \
    asm volatile("mma.sync.aligned.m16n8k16.row.col.f32.bf16.bf16.f32 " \
                 "{%0,%1,%2,%3}, {%4,%5,%6,%7}, {%8,%9}, {%0,%1,%2,%3};" \
                 : "+f"((d)[0]), "+f"((d)[1]), "+f"((d)[2]), "+f"((d)[3]) \
                 : "r"((a)[0]), "r"((a)[1]), "r"((a)[2]), "r"((a)[3]), \
                   "r"((b)[0]), "r"((b)[1]))

// fast exp on the FMA pipe
__device__ __forceinline__ float fexp(float x) {
    float y = x * 1.4426950408889634f;
    y = fminf(fmaxf(y, -120.f), 120.f);
    float fy = floorf(y);
    float f = y - fy;
    float p = 1.5403530e-4f;
    p = fmaf(p, f, 1.3333558e-3f);
    p = fmaf(p, f, 9.6181291e-3f);
    p = fmaf(p, f, 5.5504109e-2f);
    p = fmaf(p, f, 2.4022651e-1f);
    p = fmaf(p, f, 6.9314718e-1f);
    p = fmaf(p, f, 1.0f);
    int e = (int)fy;
    return p * __int_as_float((e + 127) << 23);
}

__device__ __forceinline__ void split_store4(__nv_bfloat16* hi, __nv_bfloat16* lo, float4 v) {
    __nv_bfloat16 h0 = __float2bfloat16(v.x), h1 = __float2bfloat16(v.y);
    __nv_bfloat16 h2 = __float2bfloat16(v.z), h3 = __float2bfloat16(v.w);
    __nv_bfloat162 hp0(h0, h1), hp1(h2, h3);
    __nv_bfloat162 lp0 = __floats2bfloat162_rn(v.x - __bfloat162float(h0),
                                               v.y - __bfloat162float(h1));
    __nv_bfloat162 lp1 = __floats2bfloat162_rn(v.z - __bfloat162float(h2),
                                               v.w - __bfloat162float(h3));
    *(uint2*)hi = make_uint2(*(uint32_t*)&hp0, *(uint32_t*)&hp1);
    *(uint2*)lo = make_uint2(*(uint32_t*)&lp0, *(uint32_t*)&lp1);
}

// ---------------------------------------------------------------------------
// Kernel 1: scores = Q @ K^T via mma.sync bf16 split (3 terms), two 64-col
// K-halves staged serially. 2 CTAs/SM (128-reg cap, 73.7KB smem).
// ---------------------------------------------------------------------------
#define LDE2 72
#define PLANE2 (128 * LDE2)

__global__ __launch_bounds__(256, 2) void qk_gemm_mma(
    const float* __restrict__ Q, const float* __restrict__ K)
{
    const int kt = blockIdx.x;
    const int qt = blockIdx.y;
    if (kt > qt) return;
    const int bh = blockIdx.z;

    extern __shared__ __align__(16) __nv_bfloat16 smem[];
    __nv_bfloat16* QH = smem;
    __nv_bfloat16* QL = smem + PLANE2;
    __nv_bfloat16* KH = smem + 2 * PLANE2;
    __nv_bfloat16* KL = smem + 3 * PLANE2;

    const int tid = threadIdx.x;
    const float* Qb = Q + ((size_t)bh * SS + (size_t)qt * 128) * DD;
    const float* Kb = K + ((size_t)bh * SS + (size_t)kt * 128) * DD;

    const int warp = tid >> 5, lane = tid & 31;
    const int m0 = (warp & 3) * 32;
    const int n0 = (warp >> 2) * 64;
    const int lrow = lane & 15;
    const int lgrp = lane >> 4;

    float acc[2][8][4] = {};

    for (int half = 0; half < 2; half++) {
        if (half) __syncthreads();
        for (int i = tid; i < 128 * 16; i += 256) {
            const int row = i >> 4, k = (i & 15) * 4;
            float4 v = *(const float4*)&Qb[(size_t)row * DD + half * 64 + k];
            split_store4(&QH[row * LDE2 + k], &QL[row * LDE2 + k], v);
            float4 u = *(const float4*)&Kb[(size_t)row * DD + half * 64 + k];
            split_store4(&KH[row * LDE2 + k], &KL[row * LDE2 + k], u);
        }
        __syncthreads();

        #pragma unroll
        for (int ks = 0; ks < 4; ks++) {
            const int kb = ks * 16;
            uint32_t ah[2][4], al[2][4];
            #pragma unroll
            for (int mi = 0; mi < 2; mi++) {
                uint32_t aH = smem_u32(&QH[(m0 + mi * 16 + lrow) * LDE2 + kb + lgrp * 8]);
                LDMATRIX_X4(ah[mi][0], ah[mi][1], ah[mi][2], ah[mi][3], aH);
                uint32_t aL = smem_u32(&QL[(m0 + mi * 16 + lrow) * LDE2 + kb + lgrp * 8]);
                LDMATRIX_X4(al[mi][0], al[mi][1], al[mi][2], al[mi][3], aL);
            }
            #pragma unroll
            for (int nfi = 0; nfi < 4; nfi++) {
                uint32_t bh4[4], bl4[4];
                uint32_t bHaddr = smem_u32(&KH[(n0 + nfi * 16 + lrow) * LDE2 + kb + lgrp * 8]);
                LDMATRIX_X4(bh4[0], bh4[1], bh4[2], bh4[3], bHaddr);
                uint32_t bLaddr = smem_u32(&KL[(n0 + nfi * 16 + lrow) * LDE2 + kb + lgrp * 8]);
                LDMATRIX_X4(bl4[0], bl4[1], bl4[2], bl4[3], bLaddr);

                uint32_t bh0[2] = {bh4[0], bh4[2]}, bh1[2] = {bh4[1], bh4[3]};
                uint32_t bl0[2] = {bl4[0], bl4[2]}, bl1[2] = {bl4[1], bl4[3]};

                #pragma unroll
                for (int mi = 0; mi < 2; mi++) {
                    MMA_BF16(acc[mi][2 * nfi],     ah[mi], bh0);
                    MMA_BF16(acc[mi][2 * nfi],     ah[mi], bl0);
                    MMA_BF16(acc[mi][2 * nfi],     al[mi], bh0);
                    MMA_BF16(acc[mi][2 * nfi + 1], ah[mi], bh1);
                    MMA_BF16(acc[mi][2 * nfi + 1], ah[mi], bl1);
                    MMA_BF16(acc[mi][2 * nfi + 1], al[mi], bh1);
                }
            }
        }
    }

    float* out = g_scores + (size_t)bh * SS * SS;
    const int g = lane >> 2, t2 = (lane & 3) * 2;
    #pragma unroll
    for (int mi = 0; mi < 2; mi++) {
        const int r1 = qt * 128 + m0 + mi * 16 + g;
        const int r2 = r1 + 8;
        #pragma unroll
        for (int nf = 0; nf < 8; nf++) {
            const int col = kt * 128 + n0 + nf * 8 + t2;
            *(float2*)&out[(size_t)r1 * SS + col] = make_float2(acc[mi][nf][0], acc[mi][nf][1]);
            *(float2*)&out[(size_t)r2 * SS + col] = make_float2(acc[mi][nf][2], acc[mi][nf][3]);
        }
    }
}

// ---------------------------------------------------------------------------
// Kernel 2 (fused): conv + no-max softmax + @V via mma.sync.
// Per 64-key chunk: stage scores with (5,±5) halo -> conv*scale -> exp ->
// split-bf16 P; stage split-bf16 V; 3-term HMMA; normalize at the end.
// ---------------------------------------------------------------------------
#define PV_LDP 72    // P plane stride (bf16)
#define PV_LDV 136   // V plane stride (bf16)
#define S_LD 76      // score halo tile stride (float)

__global__ __launch_bounds__(256, 2) void conv_softmax_pv(
    const float* __restrict__ V, const float* __restrict__ W,
    float* __restrict__ O)
{
    const int qt = blockIdx.x;    // 0..15
    const int bh = blockIdx.y;
    const int q0 = qt * 64;

    const float* Sb = g_scores + (size_t)bh * SS * SS;
    const float* Vb = V + (size_t)bh * SS * DD;
    float* Ob = O + (size_t)bh * SS * DD;

    extern __shared__ __align__(16) char dsm[];
    float* Ssh = (float*)dsm;                           // 69 x 76
    __nv_bfloat16* Ph = (__nv_bfloat16*)(Ssh + 69 * S_LD);
    __nv_bfloat16* Pl = Ph + 64 * PV_LDP;
    __nv_bfloat16* Vh = Pl + 64 * PV_LDP;               // 64 x 136
    __nv_bfloat16* Vl = Vh + 64 * PV_LDV;
    float* rowSum = (float*)(Vl + 64 * PV_LDV);         // 64
    float* ws = rowSum + 64;                            // 66

    const int tid = threadIdx.x;
    const int warp = tid >> 5, lane = tid & 31;
    const int m0 = (warp & 1) * 32;
    const int n0 = (warp >> 1) * 32;

    const int h = bh % NH;
    if (tid < 66) ws[tid] = W[h * 66 + tid];

    const int pr = tid >> 2;            // 0..63 (fixed q-row)
    const int pc = (tid & 3) * 16;      // 0..48 (16-key segment)
    const int pq = q0 + pr;
    float psum = 0.f;

    float acc[2][4][4] = {};

    const int lrow = lane & 15;
    const int lgrp = lane >> 4;
    const int bi = lane >> 3;
    const int brow = lane & 7;

    const float scale = 0.088388347648318447f;  // 1/sqrt(128)

    for (int kc = 0; kc < q0 + 64; kc += 64) {
        if (kc) __syncthreads();

        // stage scores halo tile: rows q0-5..q0+63, cols kc-5..kc+68,
        // causal-masked at load (k<=q; also guards OOB)
        for (int i = tid; i < 69 * 74; i += 256) {
            const int rr = i / 74, cc = i % 74;
            const int q = q0 - 5 + rr;
            const int k = kc - 5 + cc;
            float v = 0.f;
            if (q >= 0 && k >= 0 && k <= q) v = Sb[(size_t)q * SS + k];
            Ssh[rr * S_LD + cc] = v;
        }
        // stage V chunk 64 x 128 -> hi/lo
        for (int i = tid; i < 64 * 32; i += 256) {
            const int kr = i >> 5, c = (i & 31) * 4;
            float4 v = *(const float4*)&Vb[(size_t)(kc + kr) * DD + c];
            split_store4(&Vh[kr * PV_LDV + c], &Vl[kr * PV_LDV + c], v);
        }
        __syncthreads();

        // conv -> scale -> exp -> split-bf16 P (16 outputs per thread)
        {
            float out[16] = {};
            #pragma unroll
            for (int dq = 0; dq < 6; dq++) {
                float win[28];
                const float* srow = &Ssh[(pr + dq) * S_LD + pc];
                #pragma unroll
                for (int t4 = 0; t4 < 7; t4++)
                    *(float4*)&win[t4 * 4] = *(const float4*)&srow[t4 * 4];
                #pragma unroll
                for (int dk = 0; dk < 11; dk++) {
                    float w = ws[dq * 11 + dk];
                    #pragma unroll
                    for (int j = 0; j < 16; j++) out[j] += w * win[j + dk];
                }
            }
            #pragma unroll
            for (int j4 = 0; j4 < 4; j4++) {
                const int kbase = kc + pc + j4 * 4;
                float e0 = (kbase + 0 <= pq) ? fexp(out[j4*4+0] * scale) : 0.f;
                float e1 = (kbase + 1 <= pq) ? fexp(out[j4*4+1] * scale) : 0.f;
                float e2 = (kbase + 2 <= pq) ? fexp(out[j4*4+2] * scale) : 0.f;
                float e3 = (kbase + 3 <= pq) ? fexp(out[j4*4+3] * scale) : 0.f;
                psum += (e0 + e1) + (e2 + e3);
                split_store4(&Ph[pr * PV_LDP + pc + j4 * 4],
                             &Pl[pr * PV_LDP + pc + j4 * 4],
                             make_float4(e0, e1, e2, e3));
            }
        }
        __syncthreads();

        // 3-term HMMA: O += Phi*Vhi + Phi*Vlo + Plo*Vhi
        #pragma unroll
        for (int ks = 0; ks < 4; ks++) {
            const int kb = ks * 16;
            uint32_t ah[2][4], al[2][4];
            #pragma unroll
            for (int mi = 0; mi < 2; mi++) {
                uint32_t aH = smem_u32(&Ph[(m0 + mi * 16 + lrow) * PV_LDP + kb + lgrp * 8]);
                LDMATRIX_X4(ah[mi][0], ah[mi][1], ah[mi][2], ah[mi][3], aH);
                uint32_t aL = smem_u32(&Pl[(m0 + mi * 16 + lrow) * PV_LDP + kb + lgrp * 8]);
                LDMATRIX_X4(al[mi][0], al[mi][1], al[mi][2], al[mi][3], aL);
            }
            #pragma unroll
            for (int ng = 0; ng < 2; ng++) {
                const int vrow = kb + (bi & 1) * 8 + brow;
                const int vcol = n0 + ng * 16 + (bi >> 1) * 8;
                uint32_t bh4[4], bl4[4];
                uint32_t bHaddr = smem_u32(&Vh[vrow * PV_LDV + vcol]);
                LDMATRIX_X4_T(bh4[0], bh4[1], bh4[2], bh4[3], bHaddr);
                uint32_t bLaddr = smem_u32(&Vl[vrow * PV_LDV + vcol]);
                LDMATRIX_X4_T(bl4[0], bl4[1], bl4[2], bl4[3], bLaddr);

                uint32_t bh0[2] = {bh4[0], bh4[1]}, bh1[2] = {bh4[2], bh4[3]};
                uint32_t bl0[2] = {bl4[0], bl4[1]}, bl1[2] = {bl4[2], bl4[3]};

                #pragma unroll
                for (int mi = 0; mi < 2; mi++) {
                    MMA_BF16(acc[mi][2 * ng],     ah[mi], bh0);
                    MMA_BF16(acc[mi][2 * ng],     ah[mi], bl0);
                    MMA_BF16(acc[mi][2 * ng],     al[mi], bh0);
                    MMA_BF16(acc[mi][2 * ng + 1], ah[mi], bh1);
                    MMA_BF16(acc[mi][2 * ng + 1], ah[mi], bl1);
                    MMA_BF16(acc[mi][2 * ng + 1], al[mi], bh1);
                }
            }
        }
    }

    // reduce per-row sums (quad lanes share row pr)
    psum += __shfl_xor_sync(0xffffffffu, psum, 1);
    psum += __shfl_xor_sync(0xffffffffu, psum, 2);
    if ((tid & 3) == 0) rowSum[pr] = psum;
    __syncthreads();

    const int g = lane >> 2, t2 = (lane & 3) * 2;
    #pragma unroll
    for (int mi = 0; mi < 2; mi++) {
        const int lr1 = m0 + mi * 16 + g;
        const int lr2 = lr1 + 8;
        const float inv1 = 1.f / rowSum[lr1];
        const float inv2 = 1.f / rowSum[lr2];
        #pragma unroll
        for (int nf = 0; nf < 4; nf++) {
            const int col = n0 + nf * 8 + t2;
            *(float2*)&Ob[(size_t)(q0 + lr1) * DD + col] =
                make_float2(acc[mi][nf][0] * inv1, acc[mi][nf][1] * inv1);
            *(float2*)&Ob[(size_t)(q0 + lr2) * DD + col] =
                make_float2(acc[mi][nf][2] * inv2, acc[mi][nf][3] * inv2);
        }
    }
}

// ---------------------------------------------------------------------------
extern "C" void kernel_launch(void* const* d_in, const int* in_sizes, int n_in,
                              void* d_out, int out_size)
{
    const float* Q = (const float*)d_in[0];
    const float* K = (const float*)d_in[1];
    const float* V = (const float*)d_in[2];
    const float* W = (const float*)d_in[3];
    float* O = (float*)d_out;

    const int QK_SMEM = 4 * PLANE2 * (int)sizeof(__nv_bfloat16);  // 73728 B
    cudaFuncSetAttribute(qk_gemm_mma, cudaFuncAttributeMaxDynamicSharedMemorySize, QK_SMEM);

    const int PV_SMEM = 69 * S_LD * (int)sizeof(float)
                      + (2 * 64 * PV_LDP + 2 * 64 * PV_LDV) * (int)sizeof(__nv_bfloat16)
                      + (64 + 66) * (int)sizeof(float);           // ~74.4 KB
    cudaFuncSetAttribute(conv_softmax_pv, cudaFuncAttributeMaxDynamicSharedMemorySize, PV_SMEM);

    dim3 g1(8, 8, NBH);
    qk_gemm_mma<<<g1, 256, QK_SMEM>>>(Q, K);

    dim3 g3(16, NBH);
    conv_softmax_pv<<<g3, 256, PV_SMEM>>>(V, W, O);
}